// round 2
// baseline (speedup 1.0000x reference)
#include <cuda_runtime.h>
#include <math.h>

#define SEQ  4096
#define HDIM 768
#define NHEAD 12
#define HD   64

// Scratch (static device allocs are allowed; cudaMalloc is not)
__device__ float g_q[NHEAD * SEQ * HD];
__device__ float g_k[NHEAD * SEQ * HD];
__device__ float g_v[NHEAD * SEQ * HD];
__device__ float g_ctx[NHEAD * SEQ * HD];
__device__ float g_madd[SEQ];

// ---------------------------------------------------------------------------
// Mask -> additive bias: madd[j] = mask[j] ? -1e9 : 0
// Mask arrives as int32 (bool is not a harness transport dtype).
// ---------------------------------------------------------------------------
__global__ void mask_kernel(const int* __restrict__ mask) {
    int i = blockIdx.x * blockDim.x + threadIdx.x;
    if (i < SEQ) g_madd[i] = mask[i] ? -1e9f : 0.0f;
}

// ---------------------------------------------------------------------------
// QKV projection: out = x @ W^T + b   (NT GEMM, M=4096, N=768, K=768)
// Output written head-major: dst[head][s][d]
// grid = (12, 64, 3), block = 256
// ---------------------------------------------------------------------------
__global__ __launch_bounds__(256)
void qkv_kernel(const float* __restrict__ x,
                const float* __restrict__ Wq, const float* __restrict__ bq,
                const float* __restrict__ Wk, const float* __restrict__ bk,
                const float* __restrict__ Wv, const float* __restrict__ bv) {
    const float* W;
    const float* bias;
    float* dst;
    int z = blockIdx.z;
    if (z == 0)      { W = Wq; bias = bq; dst = g_q; }
    else if (z == 1) { W = Wk; bias = bk; dst = g_k; }
    else             { W = Wv; bias = bv; dst = g_v; }

    __shared__ float As[32][68];   // [k][m]
    __shared__ float Bs[32][68];   // [k][n]

    int tid = threadIdx.x;
    int tx = tid & 15, ty = tid >> 4;
    int mbase = blockIdx.y * 64;
    int nbase = blockIdx.x * 64;

    float acc[4][4] = {};

    for (int kb = 0; kb < HDIM; kb += 32) {
        #pragma unroll
        for (int r = 0; r < 2; r++) {
            int idx = r * 256 + tid;        // 0..511
            int row = idx >> 3;             // 0..63 (m or n)
            int c   = idx & 7;              // k-chunk of 4
            float4 av = *(const float4*)(x + (size_t)(mbase + row) * HDIM + kb + c * 4);
            As[c*4+0][row] = av.x; As[c*4+1][row] = av.y;
            As[c*4+2][row] = av.z; As[c*4+3][row] = av.w;
            float4 bv4 = *(const float4*)(W + (size_t)(nbase + row) * HDIM + kb + c * 4);
            Bs[c*4+0][row] = bv4.x; Bs[c*4+1][row] = bv4.y;
            Bs[c*4+2][row] = bv4.z; Bs[c*4+3][row] = bv4.w;
        }
        __syncthreads();

        #pragma unroll 8
        for (int k = 0; k < 32; k++) {
            float4 a4 = *(const float4*)&As[k][ty * 4];
            float4 b4 = *(const float4*)&Bs[k][tx * 4];
            float av[4] = {a4.x, a4.y, a4.z, a4.w};
            float bv2[4] = {b4.x, b4.y, b4.z, b4.w};
            #pragma unroll
            for (int a = 0; a < 4; a++)
                #pragma unroll
                for (int b = 0; b < 4; b++)
                    acc[a][b] += av[a] * bv2[b];
        }
        __syncthreads();
    }

    // Epilogue: n-tile == exactly one head (64 cols)
    int head = nbase >> 6;
    #pragma unroll
    for (int a = 0; a < 4; a++) {
        int s = mbase + ty * 4 + a;
        float4 o;
        o.x = acc[a][0] + bias[nbase + tx * 4 + 0];
        o.y = acc[a][1] + bias[nbase + tx * 4 + 1];
        o.z = acc[a][2] + bias[nbase + tx * 4 + 2];
        o.w = acc[a][3] + bias[nbase + tx * 4 + 3];
        *(float4*)(dst + ((size_t)head * SEQ + s) * HD + tx * 4) = o;
    }
}

// ---------------------------------------------------------------------------
// Flash attention: one block = (head, 64-query tile). 256 threads (4 warps).
// Online softmax; rows of S-tile owned by 16-lane groups (shfl width 16).
// grid = (64, 12), dynamic smem.
// ---------------------------------------------------------------------------
#define FLASH_SMEM ((4 * 64 * 68 + 64) * 4)

__global__ __launch_bounds__(256)
void flash_kernel() {
    extern __shared__ float smem[];
    float (*Qs)[68] = (float (*)[68])(smem);                 // [d][i]
    float (*Ks)[68] = (float (*)[68])(smem + 64 * 68);       // [d][j]
    float (*Vs)[68] = (float (*)[68])(smem + 2 * 64 * 68);   // [j][d]
    float (*Ps)[68] = (float (*)[68])(smem + 3 * 64 * 68);   // [j][i]
    float* madds = smem + 4 * 64 * 68;                       // [64]

    int tid = threadIdx.x;
    int tx = tid & 15, ty = tid >> 4;
    int h = blockIdx.y;
    int qb = blockIdx.x * 64;

    const float* Qg = g_q + ((size_t)h * SEQ + qb) * HD;
    const float* Kg = g_k + (size_t)h * SEQ * HD;
    const float* Vg = g_v + (size_t)h * SEQ * HD;

    // Load Q tile (transposed into [d][i])
    #pragma unroll
    for (int r = 0; r < 4; r++) {
        int idx = r * 256 + tid;     // 0..1023
        int i = idx >> 4, c = idx & 15;
        float4 v = *(const float4*)(Qg + (size_t)i * HD + c * 4);
        Qs[c*4+0][i] = v.x; Qs[c*4+1][i] = v.y;
        Qs[c*4+2][i] = v.z; Qs[c*4+3][i] = v.w;
    }

    const float NEG_INF = -3.4e38f;
    float m[4] = {NEG_INF, NEG_INF, NEG_INF, NEG_INF};
    float l[4] = {0.f, 0.f, 0.f, 0.f};
    float acc[4][4] = {};

    for (int kt = 0; kt < SEQ; kt += 64) {
        // Load K (transposed) and V (natural) tiles
        #pragma unroll
        for (int r = 0; r < 4; r++) {
            int idx = r * 256 + tid;
            int j = idx >> 4, c = idx & 15;
            float4 kv = *(const float4*)(Kg + (size_t)(kt + j) * HD + c * 4);
            Ks[c*4+0][j] = kv.x; Ks[c*4+1][j] = kv.y;
            Ks[c*4+2][j] = kv.z; Ks[c*4+3][j] = kv.w;
            float4 vv = *(const float4*)(Vg + (size_t)(kt + j) * HD + c * 4);
            *(float4*)&Vs[j][c * 4] = vv;
        }
        if (tid < 64) madds[tid] = g_madd[kt + tid];
        __syncthreads();

        // S = Q K^T (64x64), 4x4 per thread
        float sreg[4][4] = {};
        #pragma unroll 8
        for (int d = 0; d < 64; d++) {
            float4 q4 = *(const float4*)&Qs[d][ty * 4];
            float4 k4 = *(const float4*)&Ks[d][tx * 4];
            float qv[4] = {q4.x, q4.y, q4.z, q4.w};
            float kv2[4] = {k4.x, k4.y, k4.z, k4.w};
            #pragma unroll
            for (int a = 0; a < 4; a++)
                #pragma unroll
                for (int b = 0; b < 4; b++)
                    sreg[a][b] += qv[a] * kv2[b];
        }

        // scale + mask
        float mb[4];
        #pragma unroll
        for (int b = 0; b < 4; b++) mb[b] = madds[tx * 4 + b];
        #pragma unroll
        for (int a = 0; a < 4; a++)
            #pragma unroll
            for (int b = 0; b < 4; b++)
                sreg[a][b] = sreg[a][b] * 0.125f + mb[b];

        // Online softmax update per row (16-lane groups share a row)
        #pragma unroll
        for (int a = 0; a < 4; a++) {
            float rm = fmaxf(fmaxf(sreg[a][0], sreg[a][1]), fmaxf(sreg[a][2], sreg[a][3]));
            #pragma unroll
            for (int o = 8; o > 0; o >>= 1)
                rm = fmaxf(rm, __shfl_xor_sync(0xffffffffu, rm, o, 16));
            float mn = fmaxf(m[a], rm);
            float alpha = __expf(m[a] - mn);
            float rs = 0.f;
            #pragma unroll
            for (int b = 0; b < 4; b++) {
                float p = __expf(sreg[a][b] - mn);
                sreg[a][b] = p;
                rs += p;
            }
            #pragma unroll
            for (int o = 8; o > 0; o >>= 1)
                rs += __shfl_xor_sync(0xffffffffu, rs, o, 16);
            l[a] = l[a] * alpha + rs;
            m[a] = mn;
            #pragma unroll
            for (int b = 0; b < 4; b++) acc[a][b] *= alpha;
        }

        // P -> smem [j][i]
        #pragma unroll
        for (int a = 0; a < 4; a++)
            #pragma unroll
            for (int b = 0; b < 4; b++)
                Ps[tx * 4 + b][ty * 4 + a] = sreg[a][b];
        __syncthreads();

        // acc += P @ V
        #pragma unroll 8
        for (int j = 0; j < 64; j++) {
            float4 p4 = *(const float4*)&Ps[j][ty * 4];
            float4 v4 = *(const float4*)&Vs[j][tx * 4];
            float pv[4] = {p4.x, p4.y, p4.z, p4.w};
            float vv2[4] = {v4.x, v4.y, v4.z, v4.w};
            #pragma unroll
            for (int a = 0; a < 4; a++)
                #pragma unroll
                for (int b = 0; b < 4; b++)
                    acc[a][b] += pv[a] * vv2[b];
        }
        __syncthreads();
    }

    // ctx = acc / l
    float* Og = g_ctx + ((size_t)h * SEQ + qb) * HD;
    #pragma unroll
    for (int a = 0; a < 4; a++) {
        float inv = 1.0f / l[a];
        float4 o;
        o.x = acc[a][0] * inv; o.y = acc[a][1] * inv;
        o.z = acc[a][2] * inv; o.w = acc[a][3] * inv;
        *(float4*)(Og + (size_t)(ty * 4 + a) * HD + tx * 4) = o;
    }
}

// ---------------------------------------------------------------------------
// Output projection: out = ctx @ Wo^T + bo   (ctx read from [NH][S][D])
// grid = (12, 64), block = 256
// ---------------------------------------------------------------------------
__global__ __launch_bounds__(256)
void oproj_kernel(const float* __restrict__ Wo, const float* __restrict__ bo,
                  float* __restrict__ out) {
    __shared__ float As[32][68];   // [k][m]
    __shared__ float Bs[32][68];   // [k][n]

    int tid = threadIdx.x;
    int tx = tid & 15, ty = tid >> 4;
    int mbase = blockIdx.y * 64;
    int nbase = blockIdx.x * 64;

    float acc[4][4] = {};

    for (int kb = 0; kb < HDIM; kb += 32) {
        #pragma unroll
        for (int r = 0; r < 2; r++) {
            int idx = r * 256 + tid;
            int row = idx >> 3;
            int c   = idx & 7;
            int hg = kb + c * 4;    // 4-aligned, stays within one 64-head
            const float* src = g_ctx + ((size_t)(hg >> 6) * SEQ + (mbase + row)) * HD + (hg & 63);
            float4 av = *(const float4*)src;
            As[c*4+0][row] = av.x; As[c*4+1][row] = av.y;
            As[c*4+2][row] = av.z; As[c*4+3][row] = av.w;
            float4 wv = *(const float4*)(Wo + (size_t)(nbase + row) * HDIM + kb + c * 4);
            Bs[c*4+0][row] = wv.x; Bs[c*4+1][row] = wv.y;
            Bs[c*4+2][row] = wv.z; Bs[c*4+3][row] = wv.w;
        }
        __syncthreads();

        #pragma unroll 8
        for (int k = 0; k < 32; k++) {
            float4 a4 = *(const float4*)&As[k][ty * 4];
            float4 b4 = *(const float4*)&Bs[k][tx * 4];
            float av[4] = {a4.x, a4.y, a4.z, a4.w};
            float bv2[4] = {b4.x, b4.y, b4.z, b4.w};
            #pragma unroll
            for (int a = 0; a < 4; a++)
                #pragma unroll
                for (int b = 0; b < 4; b++)
                    acc[a][b] += av[a] * bv2[b];
        }
        __syncthreads();
    }

    #pragma unroll
    for (int a = 0; a < 4; a++) {
        int s = mbase + ty * 4 + a;
        float4 o;
        o.x = acc[a][0] + bo[nbase + tx * 4 + 0];
        o.y = acc[a][1] + bo[nbase + tx * 4 + 1];
        o.z = acc[a][2] + bo[nbase + tx * 4 + 2];
        o.w = acc[a][3] + bo[nbase + tx * 4 + 3];
        *(float4*)(out + (size_t)s * HDIM + nbase + tx * 4) = o;
    }
}

// ---------------------------------------------------------------------------
extern "C" void kernel_launch(void* const* d_in, const int* in_sizes, int n_in,
                              void* d_out, int out_size) {
    const float* x  = (const float*)d_in[0];
    const float* Wq = (const float*)d_in[1];
    const float* bq = (const float*)d_in[2];
    const float* Wk = (const float*)d_in[3];
    const float* bk = (const float*)d_in[4];
    const float* Wv = (const float*)d_in[5];
    const float* bv = (const float*)d_in[6];
    const float* Wo = (const float*)d_in[7];
    const float* bo = (const float*)d_in[8];
    const int*   mask = (const int*)d_in[9];
    float* out = (float*)d_out;

    cudaFuncSetAttribute(flash_kernel, cudaFuncAttributeMaxDynamicSharedMemorySize,
                         FLASH_SMEM);

    mask_kernel<<<(SEQ + 255) / 256, 256>>>(mask);
    qkv_kernel<<<dim3(HDIM / 64, SEQ / 64, 3), 256>>>(x, Wq, bq, Wk, bk, Wv, bv);
    flash_kernel<<<dim3(SEQ / 64, NHEAD), 256, FLASH_SMEM>>>();
    oproj_kernel<<<dim3(HDIM / 64, SEQ / 64), 256>>>(Wo, bo, out);
}

// round 3
// speedup vs baseline: 2.1405x; 2.1405x over previous
#include <cuda_runtime.h>
#include <math.h>
#include <stdint.h>

#define SEQ  4096
#define HDIM 768
#define NHEAD 12
#define HD   64

// Scratch
__device__ float g_q[NHEAD * SEQ * HD];
__device__ float g_k[NHEAD * SEQ * HD];
__device__ float g_v[NHEAD * SEQ * HD];
__device__ float g_k2[NHEAD * SEQ * HD];   // compacted K
__device__ float g_v2[NHEAD * SEQ * HD];   // compacted V
__device__ float g_ctx[NHEAD * SEQ * HD];
__device__ int   g_kidx[SEQ];
__device__ int   g_cnt;

__device__ __forceinline__ uint32_t f2tf(float f) {
    uint32_t u;
    asm("cvt.rna.tf32.f32 %0, %1;" : "=r"(u) : "f"(f));
    return u;
}

__device__ __forceinline__ void mma_tf32(float c[4],
                                         uint32_t a0, uint32_t a1, uint32_t a2, uint32_t a3,
                                         uint32_t b0, uint32_t b1) {
    asm volatile("mma.sync.aligned.m16n8k8.row.col.f32.tf32.tf32.f32 "
                 "{%0,%1,%2,%3}, {%4,%5,%6,%7}, {%8,%9}, {%0,%1,%2,%3};"
                 : "+f"(c[0]), "+f"(c[1]), "+f"(c[2]), "+f"(c[3])
                 : "r"(a0), "r"(a1), "r"(a2), "r"(a3), "r"(b0), "r"(b1));
}

// ---------------------------------------------------------------------------
// Compaction: indices of UNMASKED columns (mask==0 keeps; mask!=0 -> -1e9 -> 0)
// One block, 1024 threads, 4 elems each. Stable (order-preserving) scan.
// ---------------------------------------------------------------------------
__global__ void compact_kernel(const int* __restrict__ mask) {
    __shared__ int wsum[32];
    int tid = threadIdx.x, lane = tid & 31, wid = tid >> 5;
    int f[4];
    int c = 0;
    #pragma unroll
    for (int r = 0; r < 4; r++) {
        f[r] = (mask[tid * 4 + r] == 0) ? 1 : 0;
        c += f[r];
    }
    int inc = c;
    #pragma unroll
    for (int o = 1; o < 32; o <<= 1) {
        int n = __shfl_up_sync(0xffffffffu, inc, o);
        if (lane >= o) inc += n;
    }
    if (lane == 31) wsum[wid] = inc;
    __syncthreads();
    if (wid == 0) {
        int v = wsum[lane];
        int s = v;
        #pragma unroll
        for (int o = 1; o < 32; o <<= 1) {
            int n = __shfl_up_sync(0xffffffffu, s, o);
            if (lane >= o) s += n;
        }
        wsum[lane] = s - v;  // exclusive
        if (lane == 31) g_cnt = s;
    }
    __syncthreads();
    int base = wsum[wid] + inc - c;
    #pragma unroll
    for (int r = 0; r < 4; r++) {
        if (f[r]) g_kidx[base++] = tid * 4 + r;
    }
}

// ---------------------------------------------------------------------------
// Gather compacted K/V rows. grid (SEQ/8, NHEAD), block 256 (8 warps, 1 row/warp)
// ---------------------------------------------------------------------------
__global__ __launch_bounds__(256)
void gather_kernel() {
    int h = blockIdx.y;
    int jr = blockIdx.x * 8 + (threadIdx.x >> 5);
    int lane = threadIdx.x & 31;
    int cnt = g_cnt;
    if (jr >= cnt) return;
    int src = g_kidx[jr];
    const float2* ks = (const float2*)(g_k + ((size_t)h * SEQ + src) * HD);
    float2*       kd = (float2*)(g_k2 + ((size_t)h * SEQ + jr) * HD);
    kd[lane] = ks[lane];
    const float2* vs = (const float2*)(g_v + ((size_t)h * SEQ + src) * HD);
    float2*       vd = (float2*)(g_v2 + ((size_t)h * SEQ + jr) * HD);
    vd[lane] = vs[lane];
}

// ---------------------------------------------------------------------------
// QKV projection (fp32 SIMT, unchanged): out = x @ W^T + b, head-major output
// ---------------------------------------------------------------------------
__global__ __launch_bounds__(256)
void qkv_kernel(const float* __restrict__ x,
                const float* __restrict__ Wq, const float* __restrict__ bq,
                const float* __restrict__ Wk, const float* __restrict__ bk,
                const float* __restrict__ Wv, const float* __restrict__ bv) {
    const float* W;
    const float* bias;
    float* dst;
    int z = blockIdx.z;
    if (z == 0)      { W = Wq; bias = bq; dst = g_q; }
    else if (z == 1) { W = Wk; bias = bk; dst = g_k; }
    else             { W = Wv; bias = bv; dst = g_v; }

    __shared__ float As[32][68];
    __shared__ float Bs[32][68];

    int tid = threadIdx.x;
    int tx = tid & 15, ty = tid >> 4;
    int mbase = blockIdx.y * 64;
    int nbase = blockIdx.x * 64;

    float acc[4][4] = {};

    for (int kb = 0; kb < HDIM; kb += 32) {
        #pragma unroll
        for (int r = 0; r < 2; r++) {
            int idx = r * 256 + tid;
            int row = idx >> 3;
            int c   = idx & 7;
            float4 av = *(const float4*)(x + (size_t)(mbase + row) * HDIM + kb + c * 4);
            As[c*4+0][row] = av.x; As[c*4+1][row] = av.y;
            As[c*4+2][row] = av.z; As[c*4+3][row] = av.w;
            float4 bv4 = *(const float4*)(W + (size_t)(nbase + row) * HDIM + kb + c * 4);
            Bs[c*4+0][row] = bv4.x; Bs[c*4+1][row] = bv4.y;
            Bs[c*4+2][row] = bv4.z; Bs[c*4+3][row] = bv4.w;
        }
        __syncthreads();

        #pragma unroll 8
        for (int k = 0; k < 32; k++) {
            float4 a4 = *(const float4*)&As[k][ty * 4];
            float4 b4 = *(const float4*)&Bs[k][tx * 4];
            float av[4] = {a4.x, a4.y, a4.z, a4.w};
            float bv2[4] = {b4.x, b4.y, b4.z, b4.w};
            #pragma unroll
            for (int a = 0; a < 4; a++)
                #pragma unroll
                for (int b = 0; b < 4; b++)
                    acc[a][b] += av[a] * bv2[b];
        }
        __syncthreads();
    }

    int head = nbase >> 6;
    #pragma unroll
    for (int a = 0; a < 4; a++) {
        int s = mbase + ty * 4 + a;
        float4 o;
        o.x = acc[a][0] + bias[nbase + tx * 4 + 0];
        o.y = acc[a][1] + bias[nbase + tx * 4 + 1];
        o.z = acc[a][2] + bias[nbase + tx * 4 + 2];
        o.w = acc[a][3] + bias[nbase + tx * 4 + 3];
        *(float4*)(dst + ((size_t)head * SEQ + s) * HD + tx * 4) = o;
    }
}

// ---------------------------------------------------------------------------
// Flash attention with tf32 mma.sync over COMPACTED keys.
// Block = (head, 64 q rows). 128 threads = 4 warps x 16 q rows each.
// Smem (uint32 tf32): Qs[64][68], Kt[64][72] (d-major), Vs[64][72], Ps[64][68]
// ---------------------------------------------------------------------------
#define FLASH_SMEM (64 * (68 + 72 + 72 + 68) * 4)

__global__ __launch_bounds__(128)
void flash_kernel() {
    extern __shared__ uint32_t sm[];
    uint32_t* Qs = sm;                  // [q][d]  stride 68
    uint32_t* Kt = Qs + 64 * 68;        // [d][j]  stride 72
    uint32_t* Vs = Kt + 64 * 72;        // [j][d]  stride 72
    uint32_t* Ps = Vs + 64 * 72;        // [q][j]  stride 68

    int tid = threadIdx.x;
    int lane = tid & 31, warp = tid >> 5;
    int g = lane >> 2, tg = lane & 3;
    int h = blockIdx.y, qb = blockIdx.x * 64;
    int wb = warp * 16;
    int cnt = g_cnt;

    // Load Q tile -> tf32 smem
    const float* Qg = g_q + ((size_t)h * SEQ + qb) * HD;
    #pragma unroll
    for (int rr = 0; rr < 8; rr++) {
        int idx = rr * 128 + tid;       // 0..1023
        int i = idx >> 4, c = idx & 15;
        float4 qv = *(const float4*)(Qg + (size_t)i * HD + c * 4);
        uint4 u = make_uint4(f2tf(qv.x), f2tf(qv.y), f2tf(qv.z), f2tf(qv.w));
        *(uint4*)&Qs[i * 68 + c * 4] = u;
    }

    float m0 = -1e30f, m1 = -1e30f, l0 = 0.f, l1 = 0.f;
    float acc[8][4] = {};

    const float* Kg = g_k2 + (size_t)h * SEQ * HD;
    const float* Vg = g_v2 + (size_t)h * SEQ * HD;

    int ntile = (cnt + 63) >> 6;
    for (int t = 0; t < ntile; t++) {
        int base = t * 64;
        __syncthreads();   // previous tile's PV reads done; also orders Q load (t=0)

        // Load K (transposed, d-major) and V (natural) as tf32; zero-pad tail
        #pragma unroll
        for (int rr = 0; rr < 8; rr++) {
            int idx = rr * 128 + tid;
            int j = idx >> 4, c = idx & 15;
            bool ok = (base + j) < cnt;
            float4 kv = ok ? *(const float4*)(Kg + (size_t)(base + j) * HD + c * 4)
                           : make_float4(0.f, 0.f, 0.f, 0.f);
            Kt[(c * 4 + 0) * 72 + j] = f2tf(kv.x);
            Kt[(c * 4 + 1) * 72 + j] = f2tf(kv.y);
            Kt[(c * 4 + 2) * 72 + j] = f2tf(kv.z);
            Kt[(c * 4 + 3) * 72 + j] = f2tf(kv.w);
            float4 vv = ok ? *(const float4*)(Vg + (size_t)(base + j) * HD + c * 4)
                           : make_float4(0.f, 0.f, 0.f, 0.f);
            uint4 u = make_uint4(f2tf(vv.x), f2tf(vv.y), f2tf(vv.z), f2tf(vv.w));
            *(uint4*)&Vs[j * 72 + c * 4] = u;
        }
        __syncthreads();

        // S = Q K^T  (warp: 16x64)
        float sc[8][4] = {};
        #pragma unroll
        for (int ks = 0; ks < 8; ks++) {
            uint32_t a0 = Qs[(wb + g)     * 68 + ks * 8 + tg];
            uint32_t a1 = Qs[(wb + g + 8) * 68 + ks * 8 + tg];
            uint32_t a2 = Qs[(wb + g)     * 68 + ks * 8 + tg + 4];
            uint32_t a3 = Qs[(wb + g + 8) * 68 + ks * 8 + tg + 4];
            #pragma unroll
            for (int nt = 0; nt < 8; nt++) {
                uint32_t b0 = Kt[(ks * 8 + tg)     * 72 + nt * 8 + g];
                uint32_t b1 = Kt[(ks * 8 + tg + 4) * 72 + nt * 8 + g];
                mma_tf32(sc[nt], a0, a1, a2, a3, b0, b1);
            }
        }

        // scale by 1/sqrt(64)
        #pragma unroll
        for (int nt = 0; nt < 8; nt++)
            #pragma unroll
            for (int e = 0; e < 4; e++)
                sc[nt][e] *= 0.125f;

        // tail: force out-of-range columns to -inf-ish
        if (base + 64 > cnt) {
            #pragma unroll
            for (int nt = 0; nt < 8; nt++) {
                int c0 = base + nt * 8 + 2 * tg;
                if (c0     >= cnt) { sc[nt][0] = -1e30f; sc[nt][2] = -1e30f; }
                if (c0 + 1 >= cnt) { sc[nt][1] = -1e30f; sc[nt][3] = -1e30f; }
            }
        }

        // online softmax (rows g and g+8 within warp tile)
        float rm0 = -1e30f, rm1 = -1e30f;
        #pragma unroll
        for (int nt = 0; nt < 8; nt++) {
            rm0 = fmaxf(rm0, fmaxf(sc[nt][0], sc[nt][1]));
            rm1 = fmaxf(rm1, fmaxf(sc[nt][2], sc[nt][3]));
        }
        rm0 = fmaxf(rm0, __shfl_xor_sync(0xffffffffu, rm0, 1));
        rm0 = fmaxf(rm0, __shfl_xor_sync(0xffffffffu, rm0, 2));
        rm1 = fmaxf(rm1, __shfl_xor_sync(0xffffffffu, rm1, 1));
        rm1 = fmaxf(rm1, __shfl_xor_sync(0xffffffffu, rm1, 2));

        float mn0 = fmaxf(m0, rm0), mn1 = fmaxf(m1, rm1);
        float al0 = __expf(m0 - mn0), al1 = __expf(m1 - mn1);
        float rs0 = 0.f, rs1 = 0.f;
        #pragma unroll
        for (int nt = 0; nt < 8; nt++) {
            float p0 = __expf(sc[nt][0] - mn0); sc[nt][0] = p0; rs0 += p0;
            float p1 = __expf(sc[nt][1] - mn0); sc[nt][1] = p1; rs0 += p1;
            float p2 = __expf(sc[nt][2] - mn1); sc[nt][2] = p2; rs1 += p2;
            float p3 = __expf(sc[nt][3] - mn1); sc[nt][3] = p3; rs1 += p3;
        }
        rs0 += __shfl_xor_sync(0xffffffffu, rs0, 1);
        rs0 += __shfl_xor_sync(0xffffffffu, rs0, 2);
        rs1 += __shfl_xor_sync(0xffffffffu, rs1, 1);
        rs1 += __shfl_xor_sync(0xffffffffu, rs1, 2);
        l0 = l0 * al0 + rs0; m0 = mn0;
        l1 = l1 * al1 + rs1; m1 = mn1;
        #pragma unroll
        for (int nt = 0; nt < 8; nt++) {
            acc[nt][0] *= al0; acc[nt][1] *= al0;
            acc[nt][2] *= al1; acc[nt][3] *= al1;
        }

        // P (tf32) -> warp-private smem rows
        #pragma unroll
        for (int nt = 0; nt < 8; nt++) {
            Ps[(wb + g)     * 68 + nt * 8 + 2 * tg]     = f2tf(sc[nt][0]);
            Ps[(wb + g)     * 68 + nt * 8 + 2 * tg + 1] = f2tf(sc[nt][1]);
            Ps[(wb + g + 8) * 68 + nt * 8 + 2 * tg]     = f2tf(sc[nt][2]);
            Ps[(wb + g + 8) * 68 + nt * 8 + 2 * tg + 1] = f2tf(sc[nt][3]);
        }
        __syncwarp();

        // acc += P @ V
        #pragma unroll
        for (int ks = 0; ks < 8; ks++) {
            uint32_t a0 = Ps[(wb + g)     * 68 + ks * 8 + tg];
            uint32_t a1 = Ps[(wb + g + 8) * 68 + ks * 8 + tg];
            uint32_t a2 = Ps[(wb + g)     * 68 + ks * 8 + tg + 4];
            uint32_t a3 = Ps[(wb + g + 8) * 68 + ks * 8 + tg + 4];
            #pragma unroll
            for (int nt = 0; nt < 8; nt++) {
                uint32_t b0 = Vs[(ks * 8 + tg)     * 72 + nt * 8 + g];
                uint32_t b1 = Vs[(ks * 8 + tg + 4) * 72 + nt * 8 + g];
                mma_tf32(acc[nt], a0, a1, a2, a3, b0, b1);
            }
        }
    }

    // epilogue: ctx = acc / l
    float i0 = 1.0f / l0, i1 = 1.0f / l1;
    float* Og = g_ctx + ((size_t)h * SEQ + qb) * HD;
    #pragma unroll
    for (int nt = 0; nt < 8; nt++) {
        float2 o0 = make_float2(acc[nt][0] * i0, acc[nt][1] * i0);
        *(float2*)&Og[(size_t)(wb + g) * HD + nt * 8 + 2 * tg] = o0;
        float2 o1 = make_float2(acc[nt][2] * i1, acc[nt][3] * i1);
        *(float2*)&Og[(size_t)(wb + g + 8) * HD + nt * 8 + 2 * tg] = o1;
    }
}

// ---------------------------------------------------------------------------
// Output projection (fp32 SIMT, unchanged)
// ---------------------------------------------------------------------------
__global__ __launch_bounds__(256)
void oproj_kernel(const float* __restrict__ Wo, const float* __restrict__ bo,
                  float* __restrict__ out) {
    __shared__ float As[32][68];
    __shared__ float Bs[32][68];

    int tid = threadIdx.x;
    int tx = tid & 15, ty = tid >> 4;
    int mbase = blockIdx.y * 64;
    int nbase = blockIdx.x * 64;

    float acc[4][4] = {};

    for (int kb = 0; kb < HDIM; kb += 32) {
        #pragma unroll
        for (int r = 0; r < 2; r++) {
            int idx = r * 256 + tid;
            int row = idx >> 3;
            int c   = idx & 7;
            int hg = kb + c * 4;
            const float* src = g_ctx + ((size_t)(hg >> 6) * SEQ + (mbase + row)) * HD + (hg & 63);
            float4 av = *(const float4*)src;
            As[c*4+0][row] = av.x; As[c*4+1][row] = av.y;
            As[c*4+2][row] = av.z; As[c*4+3][row] = av.w;
            float4 wv = *(const float4*)(Wo + (size_t)(nbase + row) * HDIM + kb + c * 4);
            Bs[c*4+0][row] = wv.x; Bs[c*4+1][row] = wv.y;
            Bs[c*4+2][row] = wv.z; Bs[c*4+3][row] = wv.w;
        }
        __syncthreads();

        #pragma unroll 8
        for (int k = 0; k < 32; k++) {
            float4 a4 = *(const float4*)&As[k][ty * 4];
            float4 b4 = *(const float4*)&Bs[k][tx * 4];
            float av[4] = {a4.x, a4.y, a4.z, a4.w};
            float bv2[4] = {b4.x, b4.y, b4.z, b4.w};
            #pragma unroll
            for (int a = 0; a < 4; a++)
                #pragma unroll
                for (int b = 0; b < 4; b++)
                    acc[a][b] += av[a] * bv2[b];
        }
        __syncthreads();
    }

    #pragma unroll
    for (int a = 0; a < 4; a++) {
        int s = mbase + ty * 4 + a;
        float4 o;
        o.x = acc[a][0] + bo[nbase + tx * 4 + 0];
        o.y = acc[a][1] + bo[nbase + tx * 4 + 1];
        o.z = acc[a][2] + bo[nbase + tx * 4 + 2];
        o.w = acc[a][3] + bo[nbase + tx * 4 + 3];
        *(float4*)(out + (size_t)s * HDIM + nbase + tx * 4) = o;
    }
}

// ---------------------------------------------------------------------------
extern "C" void kernel_launch(void* const* d_in, const int* in_sizes, int n_in,
                              void* d_out, int out_size) {
    const float* x  = (const float*)d_in[0];
    const float* Wq = (const float*)d_in[1];
    const float* bq = (const float*)d_in[2];
    const float* Wk = (const float*)d_in[3];
    const float* bk = (const float*)d_in[4];
    const float* Wv = (const float*)d_in[5];
    const float* bv = (const float*)d_in[6];
    const float* Wo = (const float*)d_in[7];
    const float* bo = (const float*)d_in[8];
    const int*   mask = (const int*)d_in[9];
    float* out = (float*)d_out;

    cudaFuncSetAttribute(flash_kernel, cudaFuncAttributeMaxDynamicSharedMemorySize,
                         FLASH_SMEM);

    compact_kernel<<<1, 1024>>>(mask);
    qkv_kernel<<<dim3(HDIM / 64, SEQ / 64, 3), 256>>>(x, Wq, bq, Wk, bk, Wv, bv);
    gather_kernel<<<dim3(SEQ / 8, NHEAD), 256>>>();
    flash_kernel<<<dim3(SEQ / 64, NHEAD), 128, FLASH_SMEM>>>();
    oproj_kernel<<<dim3(HDIM / 64, SEQ / 64), 256>>>(Wo, bo, out);
}

// round 4
// speedup vs baseline: 3.2770x; 1.5310x over previous
#include <cuda_runtime.h>
#include <math.h>
#include <stdint.h>

#define SEQ  4096
#define HDIM 768
#define NHEAD 12
#define HD   64

// Scratch
__device__ float g_q[NHEAD * SEQ * HD];
__device__ float g_k[NHEAD * SEQ * HD];
__device__ float g_v[NHEAD * SEQ * HD];
__device__ float g_k2[NHEAD * SEQ * HD];   // compacted K
__device__ float g_v2[NHEAD * SEQ * HD];   // compacted V
__device__ float g_ctx[NHEAD * SEQ * HD];
__device__ int   g_kidx[SEQ];
__device__ int   g_cnt;

__device__ __forceinline__ uint32_t f2tf(float f) {
    uint32_t u;
    asm("cvt.rna.tf32.f32 %0, %1;" : "=r"(u) : "f"(f));
    return u;
}

__device__ __forceinline__ void mma_tf32(float c[4],
                                         uint32_t a0, uint32_t a1, uint32_t a2, uint32_t a3,
                                         uint32_t b0, uint32_t b1) {
    asm volatile("mma.sync.aligned.m16n8k8.row.col.f32.tf32.tf32.f32 "
                 "{%0,%1,%2,%3}, {%4,%5,%6,%7}, {%8,%9}, {%0,%1,%2,%3};"
                 : "+f"(c[0]), "+f"(c[1]), "+f"(c[2]), "+f"(c[3])
                 : "r"(a0), "r"(a1), "r"(a2), "r"(a3), "r"(b0), "r"(b1));
}

// ---------------------------------------------------------------------------
// Compaction: stable scan of unmasked column indices (mask==0 keeps)
// ---------------------------------------------------------------------------
__global__ void compact_kernel(const int* __restrict__ mask) {
    __shared__ int wsum[32];
    int tid = threadIdx.x, lane = tid & 31, wid = tid >> 5;
    int f[4];
    int c = 0;
    #pragma unroll
    for (int r = 0; r < 4; r++) {
        f[r] = (mask[tid * 4 + r] == 0) ? 1 : 0;
        c += f[r];
    }
    int inc = c;
    #pragma unroll
    for (int o = 1; o < 32; o <<= 1) {
        int n = __shfl_up_sync(0xffffffffu, inc, o);
        if (lane >= o) inc += n;
    }
    if (lane == 31) wsum[wid] = inc;
    __syncthreads();
    if (wid == 0) {
        int v = wsum[lane];
        int s = v;
        #pragma unroll
        for (int o = 1; o < 32; o <<= 1) {
            int n = __shfl_up_sync(0xffffffffu, s, o);
            if (lane >= o) s += n;
        }
        wsum[lane] = s - v;
        if (lane == 31) g_cnt = s;
    }
    __syncthreads();
    int base = wsum[wid] + inc - c;
    #pragma unroll
    for (int r = 0; r < 4; r++) {
        if (f[r]) g_kidx[base++] = tid * 4 + r;
    }
}

// ---------------------------------------------------------------------------
// Gather compacted K/V rows.
// ---------------------------------------------------------------------------
__global__ __launch_bounds__(256)
void gather_kernel() {
    int h = blockIdx.y;
    int jr = blockIdx.x * 8 + (threadIdx.x >> 5);
    int lane = threadIdx.x & 31;
    int cnt = g_cnt;
    if (jr >= cnt) return;
    int src = g_kidx[jr];
    const float2* ks = (const float2*)(g_k + ((size_t)h * SEQ + src) * HD);
    float2*       kd = (float2*)(g_k2 + ((size_t)h * SEQ + jr) * HD);
    kd[lane] = ks[lane];
    const float2* vs = (const float2*)(g_v + ((size_t)h * SEQ + src) * HD);
    float2*       vd = (float2*)(g_v2 + ((size_t)h * SEQ + jr) * HD);
    vd[lane] = vs[lane];
}

// ---------------------------------------------------------------------------
// tf32 mma GEMM: C[M,N] = A[M,K] @ W[N,K]^T + bias.
// CTA 128x128, BK=16, 256 thr = 8 warps (4x2), warp tile 32x64.
// Fragment-permuted smem: per m16k8 (A) / k8n8-pair (B) tile, 32 lanes x 4
// words in exact mma fragment order -> one LDS.128 per fragment (pair).
// Double-buffered, one-stage LDG prefetch.
// ---------------------------------------------------------------------------
template<bool AHEAD, bool OHEAD>
__device__ __forceinline__ void gemm_body(const float* __restrict__ A,
                                          const float* __restrict__ W,
                                          const float* __restrict__ bias,
                                          float* __restrict__ dst,
                                          uint32_t* As, uint32_t* Bs) {
    int tid = threadIdx.x;
    int lane = tid & 31, warp = tid >> 5;
    int g = lane >> 2, tg = lane & 3;
    int warp_m = warp & 3, warp_n = warp >> 2;
    int mbase = blockIdx.y * 128, nbase = blockIdx.x * 128;

    int row0 = tid >> 2;            // 0..63
    int row1 = 64 + row0;
    int c4   = tid & 3;

    // Permuted STS bases: tile*128 + (row&7)*16 + slot   (element e adds e*4)
    int aT0 = ((c4 >> 1) * 8 + (row0 >> 4)) * 128 + (row0 & 7) * 16 + ((row0 >> 3) & 1) + 2 * (c4 & 1);
    int aT1 = ((c4 >> 1) * 8 + (row1 >> 4)) * 128 + (row1 & 7) * 16 + ((row1 >> 3) & 1) + 2 * (c4 & 1);
    int bT0 = ((c4 >> 1) * 8 + (row0 >> 4)) * 128 + (row0 & 7) * 16 + (c4 & 1) + 2 * ((row0 >> 3) & 1);
    int bT1 = ((c4 >> 1) * 8 + (row1 >> 4)) * 128 + (row1 & 7) * 16 + (c4 & 1) + 2 * ((row1 >> 3) & 1);

    auto ldA = [&](int row, int kb) -> float4 {
        int kg = kb + c4 * 4;
        if (AHEAD)
            return *(const float4*)(A + (((size_t)(kg >> 6)) * SEQ + (mbase + row)) * HD + (kg & 63));
        else
            return *(const float4*)(A + (size_t)(mbase + row) * HDIM + kg);
    };
    auto ldW = [&](int row, int kb) -> float4 {
        return *(const float4*)(W + (size_t)(nbase + row) * HDIM + kb + c4 * 4);
    };
    auto stsv = [&](uint32_t* buf, int base, float4 v) {
        buf[base]      = f2tf(v.x);
        buf[base + 4]  = f2tf(v.y);
        buf[base + 8]  = f2tf(v.z);
        buf[base + 12] = f2tf(v.w);
    };

    float4 ra0 = ldA(row0, 0), ra1 = ldA(row1, 0);
    float4 rb0 = ldW(row0, 0), rb1 = ldW(row1, 0);
    stsv(As, aT0, ra0); stsv(As, aT1, ra1);
    stsv(Bs, bT0, rb0); stsv(Bs, bT1, rb1);
    __syncthreads();

    float acc[2][8][4] = {};

    const int NST = HDIM / 16;   // 48 stages
    for (int s = 0; s < NST; s++) {
        int buf = (s & 1) * 2048;
        bool more = (s + 1 < NST);
        if (more) {
            int kb = (s + 1) * 16;
            ra0 = ldA(row0, kb); ra1 = ldA(row1, kb);
            rb0 = ldW(row0, kb); rb1 = ldW(row1, kb);
        }
        #pragma unroll
        for (int ks = 0; ks < 2; ks++) {
            uint4 a0 = *(uint4*)&As[buf + (ks * 8 + warp_m * 2 + 0) * 128 + lane * 4];
            uint4 a1 = *(uint4*)&As[buf + (ks * 8 + warp_m * 2 + 1) * 128 + lane * 4];
            uint4 b0 = *(uint4*)&Bs[buf + (ks * 8 + warp_n * 4 + 0) * 128 + lane * 4];
            uint4 b1 = *(uint4*)&Bs[buf + (ks * 8 + warp_n * 4 + 1) * 128 + lane * 4];
            uint4 b2 = *(uint4*)&Bs[buf + (ks * 8 + warp_n * 4 + 2) * 128 + lane * 4];
            uint4 b3 = *(uint4*)&Bs[buf + (ks * 8 + warp_n * 4 + 3) * 128 + lane * 4];
            mma_tf32(acc[0][0], a0.x, a0.y, a0.z, a0.w, b0.x, b0.y);
            mma_tf32(acc[0][1], a0.x, a0.y, a0.z, a0.w, b0.z, b0.w);
            mma_tf32(acc[0][2], a0.x, a0.y, a0.z, a0.w, b1.x, b1.y);
            mma_tf32(acc[0][3], a0.x, a0.y, a0.z, a0.w, b1.z, b1.w);
            mma_tf32(acc[0][4], a0.x, a0.y, a0.z, a0.w, b2.x, b2.y);
            mma_tf32(acc[0][5], a0.x, a0.y, a0.z, a0.w, b2.z, b2.w);
            mma_tf32(acc[0][6], a0.x, a0.y, a0.z, a0.w, b3.x, b3.y);
            mma_tf32(acc[0][7], a0.x, a0.y, a0.z, a0.w, b3.z, b3.w);
            mma_tf32(acc[1][0], a1.x, a1.y, a1.z, a1.w, b0.x, b0.y);
            mma_tf32(acc[1][1], a1.x, a1.y, a1.z, a1.w, b0.z, b0.w);
            mma_tf32(acc[1][2], a1.x, a1.y, a1.z, a1.w, b1.x, b1.y);
            mma_tf32(acc[1][3], a1.x, a1.y, a1.z, a1.w, b1.z, b1.w);
            mma_tf32(acc[1][4], a1.x, a1.y, a1.z, a1.w, b2.x, b2.y);
            mma_tf32(acc[1][5], a1.x, a1.y, a1.z, a1.w, b2.z, b2.w);
            mma_tf32(acc[1][6], a1.x, a1.y, a1.z, a1.w, b3.x, b3.y);
            mma_tf32(acc[1][7], a1.x, a1.y, a1.z, a1.w, b3.z, b3.w);
        }
        __syncthreads();
        if (more) {
            int nb = ((s + 1) & 1) * 2048;
            stsv(As + nb, aT0, ra0); stsv(As + nb, aT1, ra1);
            stsv(Bs + nb, bT0, rb0); stsv(Bs + nb, bT1, rb1);
        }
        __syncthreads();
    }

    #pragma unroll
    for (int i = 0; i < 2; i++) {
        int m0 = mbase + warp_m * 32 + i * 16 + g;
        #pragma unroll
        for (int nt = 0; nt < 8; nt++) {
            int n0 = nbase + warp_n * 64 + nt * 8 + 2 * tg;
            float bx = bias[n0], by = bias[n0 + 1];
            float2 v0 = make_float2(acc[i][nt][0] + bx, acc[i][nt][1] + by);
            float2 v1 = make_float2(acc[i][nt][2] + bx, acc[i][nt][3] + by);
            if (OHEAD) {
                float* p = dst + (((size_t)(n0 >> 6)) * SEQ + m0) * HD + (n0 & 63);
                *(float2*)p = v0;
                *(float2*)(p + 8 * HD) = v1;
            } else {
                *(float2*)(dst + (size_t)m0 * HDIM + n0) = v0;
                *(float2*)(dst + (size_t)(m0 + 8) * HDIM + n0) = v1;
            }
        }
    }
}

__global__ __launch_bounds__(256)
void qkv_kernel(const float* __restrict__ x,
                const float* __restrict__ Wq, const float* __restrict__ bq,
                const float* __restrict__ Wk, const float* __restrict__ bk,
                const float* __restrict__ Wv, const float* __restrict__ bv) {
    __shared__ __align__(16) uint32_t As[4096];
    __shared__ __align__(16) uint32_t Bs[4096];
    const float *W, *bias;
    float* dst;
    int z = blockIdx.z;
    if (z == 0)      { W = Wq; bias = bq; dst = g_q; }
    else if (z == 1) { W = Wk; bias = bk; dst = g_k; }
    else             { W = Wv; bias = bv; dst = g_v; }
    gemm_body<false, true>(x, W, bias, dst, As, Bs);
}

__global__ __launch_bounds__(256)
void oproj_kernel(const float* __restrict__ Wo, const float* __restrict__ bo,
                  float* __restrict__ out) {
    __shared__ __align__(16) uint32_t As[4096];
    __shared__ __align__(16) uint32_t Bs[4096];
    gemm_body<true, false>(g_ctx, Wo, bo, out, As, Bs);
}

// ---------------------------------------------------------------------------
// Flash attention, fragment-permuted. CTA = (head, 64 q rows), 128 thr = 4
// warps x m16. Q fragments register-resident; K/V/P in permuted smem; all
// operand fetches are LDS.128.
// ---------------------------------------------------------------------------
#define FLASH_SMEM (16384 * 4)

__global__ __launch_bounds__(128, 3)
void flash_kernel() {
    extern __shared__ uint32_t sm[];
    uint32_t* Qp = sm;            // 32 tiles (ks*4+mt)
    uint32_t* Kp = sm + 4096;     // 32 tiles (ks*4+np)
    uint32_t* Vp = sm + 8192;     // 32 tiles (ksj*4+np)
    uint32_t* Pp = sm + 12288;    // 32 tiles (warp*8+ksj)

    int tid = threadIdx.x;
    int lane = tid & 31, warp = tid >> 5;
    int g = lane >> 2, tg = lane & 3;
    int h = blockIdx.y, qb = blockIdx.x * 64;
    int cnt = g_cnt;

    // Q -> permuted smem (A layout)
    const float* Qg = g_q + ((size_t)h * SEQ + qb) * HD;
    #pragma unroll
    for (int r = 0; r < 8; r++) {
        int idx = r * 128 + tid;
        int row = idx >> 4, c4 = idx & 15;
        float4 v = *(const float4*)(Qg + (size_t)row * HD + c4 * 4);
        int base = ((c4 >> 1) * 4 + (row >> 4)) * 128 + (row & 7) * 16
                 + ((row >> 3) & 1) + 2 * (c4 & 1);
        Qp[base]      = f2tf(v.x);
        Qp[base + 4]  = f2tf(v.y);
        Qp[base + 8]  = f2tf(v.z);
        Qp[base + 12] = f2tf(v.w);
    }
    __syncthreads();
    uint4 q[8];
    #pragma unroll
    for (int ks = 0; ks < 8; ks++)
        q[ks] = *(uint4*)&Qp[(ks * 4 + warp) * 128 + lane * 4];

    float m0 = -1e30f, m1 = -1e30f, l0 = 0.f, l1 = 0.f;
    float acc[8][4] = {};

    const float* Kg = g_k2 + (size_t)h * SEQ * HD;
    const float* Vg = g_v2 + (size_t)h * SEQ * HD;
    int ntile = (cnt + 63) >> 6;

    // P-store constants
    int t2a = (2 * tg) & 3,     s2a = ((2 * tg) >> 2) * 2;
    int t2b = (2 * tg + 1) & 3, s2b = ((2 * tg + 1) >> 2) * 2;

    for (int t = 0; t < ntile; t++) {
        int kvb = t * 64;
        __syncthreads();
        // K (B layout over d) and V (B layout over j) producers
        #pragma unroll
        for (int r = 0; r < 8; r++) {
            int idx = r * 128 + tid;
            int row = idx >> 4, c4 = idx & 15;
            bool ok = (kvb + row) < cnt;
            float4 kv = ok ? *(const float4*)(Kg + (size_t)(kvb + row) * HD + c4 * 4)
                           : make_float4(0.f, 0.f, 0.f, 0.f);
            int kb2 = ((c4 >> 1) * 4 + (row >> 4)) * 128 + (row & 7) * 16
                    + (c4 & 1) + 2 * ((row >> 3) & 1);
            Kp[kb2]      = f2tf(kv.x);
            Kp[kb2 + 4]  = f2tf(kv.y);
            Kp[kb2 + 8]  = f2tf(kv.z);
            Kp[kb2 + 12] = f2tf(kv.w);
            float4 vv = ok ? *(const float4*)(Vg + (size_t)(kvb + row) * HD + c4 * 4)
                           : make_float4(0.f, 0.f, 0.f, 0.f);
            int vb2 = ((row >> 3) * 4 + (c4 >> 2)) * 128 + (row & 3) * 4
                    + ((row >> 2) & 1) + 2 * ((c4 >> 1) & 1);
            int gg = (c4 & 1) * 4;
            Vp[vb2 + (gg + 0) * 16] = f2tf(vv.x);
            Vp[vb2 + (gg + 1) * 16] = f2tf(vv.y);
            Vp[vb2 + (gg + 2) * 16] = f2tf(vv.z);
            Vp[vb2 + (gg + 3) * 16] = f2tf(vv.w);
        }
        __syncthreads();

        // S = Q K^T
        float sc[8][4] = {};
        #pragma unroll
        for (int ks = 0; ks < 8; ks++) {
            uint4 b0 = *(uint4*)&Kp[(ks * 4 + 0) * 128 + lane * 4];
            uint4 b1 = *(uint4*)&Kp[(ks * 4 + 1) * 128 + lane * 4];
            uint4 b2 = *(uint4*)&Kp[(ks * 4 + 2) * 128 + lane * 4];
            uint4 b3 = *(uint4*)&Kp[(ks * 4 + 3) * 128 + lane * 4];
            mma_tf32(sc[0], q[ks].x, q[ks].y, q[ks].z, q[ks].w, b0.x, b0.y);
            mma_tf32(sc[1], q[ks].x, q[ks].y, q[ks].z, q[ks].w, b0.z, b0.w);
            mma_tf32(sc[2], q[ks].x, q[ks].y, q[ks].z, q[ks].w, b1.x, b1.y);
            mma_tf32(sc[3], q[ks].x, q[ks].y, q[ks].z, q[ks].w, b1.z, b1.w);
            mma_tf32(sc[4], q[ks].x, q[ks].y, q[ks].z, q[ks].w, b2.x, b2.y);
            mma_tf32(sc[5], q[ks].x, q[ks].y, q[ks].z, q[ks].w, b2.z, b2.w);
            mma_tf32(sc[6], q[ks].x, q[ks].y, q[ks].z, q[ks].w, b3.x, b3.y);
            mma_tf32(sc[7], q[ks].x, q[ks].y, q[ks].z, q[ks].w, b3.z, b3.w);
        }

        #pragma unroll
        for (int nt = 0; nt < 8; nt++)
            #pragma unroll
            for (int e = 0; e < 4; e++)
                sc[nt][e] *= 0.125f;

        if (kvb + 64 > cnt) {
            #pragma unroll
            for (int nt = 0; nt < 8; nt++) {
                int c0 = kvb + nt * 8 + 2 * tg;
                if (c0     >= cnt) { sc[nt][0] = -1e30f; sc[nt][2] = -1e30f; }
                if (c0 + 1 >= cnt) { sc[nt][1] = -1e30f; sc[nt][3] = -1e30f; }
            }
        }

        // online softmax (rows g / g+8; quad shuffles over j)
        float rm0 = -1e30f, rm1 = -1e30f;
        #pragma unroll
        for (int nt = 0; nt < 8; nt++) {
            rm0 = fmaxf(rm0, fmaxf(sc[nt][0], sc[nt][1]));
            rm1 = fmaxf(rm1, fmaxf(sc[nt][2], sc[nt][3]));
        }
        rm0 = fmaxf(rm0, __shfl_xor_sync(0xffffffffu, rm0, 1));
        rm0 = fmaxf(rm0, __shfl_xor_sync(0xffffffffu, rm0, 2));
        rm1 = fmaxf(rm1, __shfl_xor_sync(0xffffffffu, rm1, 1));
        rm1 = fmaxf(rm1, __shfl_xor_sync(0xffffffffu, rm1, 2));

        float mn0 = fmaxf(m0, rm0), mn1 = fmaxf(m1, rm1);
        float al0 = __expf(m0 - mn0), al1 = __expf(m1 - mn1);
        float rs0 = 0.f, rs1 = 0.f;
        #pragma unroll
        for (int nt = 0; nt < 8; nt++) {
            float p0 = __expf(sc[nt][0] - mn0); sc[nt][0] = p0; rs0 += p0;
            float p1 = __expf(sc[nt][1] - mn0); sc[nt][1] = p1; rs0 += p1;
            float p2 = __expf(sc[nt][2] - mn1); sc[nt][2] = p2; rs1 += p2;
            float p3 = __expf(sc[nt][3] - mn1); sc[nt][3] = p3; rs1 += p3;
        }
        rs0 += __shfl_xor_sync(0xffffffffu, rs0, 1);
        rs0 += __shfl_xor_sync(0xffffffffu, rs0, 2);
        rs1 += __shfl_xor_sync(0xffffffffu, rs1, 1);
        rs1 += __shfl_xor_sync(0xffffffffu, rs1, 2);
        l0 = l0 * al0 + rs0; m0 = mn0;
        l1 = l1 * al1 + rs1; m1 = mn1;
        #pragma unroll
        for (int nt = 0; nt < 8; nt++) {
            acc[nt][0] *= al0; acc[nt][1] *= al0;
            acc[nt][2] *= al1; acc[nt][3] *= al1;
        }

        // P -> permuted A layout (k8 tile of P's k-dim == nt)
        int pb = (warp * 8) * 128 + g * 16;
        #pragma unroll
        for (int nt = 0; nt < 8; nt++) {
            int bb = pb + nt * 128;
            Pp[bb + t2a * 4 + s2a]     = f2tf(sc[nt][0]);
            Pp[bb + t2b * 4 + s2b]     = f2tf(sc[nt][1]);
            Pp[bb + t2a * 4 + s2a + 1] = f2tf(sc[nt][2]);
            Pp[bb + t2b * 4 + s2b + 1] = f2tf(sc[nt][3]);
        }
        __syncwarp();

        // acc += P @ V
        #pragma unroll
        for (int ks = 0; ks < 8; ks++) {
            uint4 pa = *(uint4*)&Pp[(warp * 8 + ks) * 128 + lane * 4];
            uint4 b0 = *(uint4*)&Vp[(ks * 4 + 0) * 128 + lane * 4];
            uint4 b1 = *(uint4*)&Vp[(ks * 4 + 1) * 128 + lane * 4];
            uint4 b2 = *(uint4*)&Vp[(ks * 4 + 2) * 128 + lane * 4];
            uint4 b3 = *(uint4*)&Vp[(ks * 4 + 3) * 128 + lane * 4];
            mma_tf32(acc[0], pa.x, pa.y, pa.z, pa.w, b0.x, b0.y);
            mma_tf32(acc[1], pa.x, pa.y, pa.z, pa.w, b0.z, b0.w);
            mma_tf32(acc[2], pa.x, pa.y, pa.z, pa.w, b1.x, b1.y);
            mma_tf32(acc[3], pa.x, pa.y, pa.z, pa.w, b1.z, b1.w);
            mma_tf32(acc[4], pa.x, pa.y, pa.z, pa.w, b2.x, b2.y);
            mma_tf32(acc[5], pa.x, pa.y, pa.z, pa.w, b2.z, b2.w);
            mma_tf32(acc[6], pa.x, pa.y, pa.z, pa.w, b3.x, b3.y);
            mma_tf32(acc[7], pa.x, pa.y, pa.z, pa.w, b3.z, b3.w);
        }
    }

    // epilogue
    float i0 = 1.0f / l0, i1 = 1.0f / l1;
    float* Og = g_ctx + ((size_t)h * SEQ + qb + warp * 16) * HD;
    #pragma unroll
    for (int nt = 0; nt < 8; nt++) {
        int col = nt * 8 + 2 * tg;
        *(float2*)&Og[(size_t)g * HD + col] =
            make_float2(acc[nt][0] * i0, acc[nt][1] * i0);
        *(float2*)&Og[(size_t)(g + 8) * HD + col] =
            make_float2(acc[nt][2] * i1, acc[nt][3] * i1);
    }
}

// ---------------------------------------------------------------------------
extern "C" void kernel_launch(void* const* d_in, const int* in_sizes, int n_in,
                              void* d_out, int out_size) {
    const float* x  = (const float*)d_in[0];
    const float* Wq = (const float*)d_in[1];
    const float* bq = (const float*)d_in[2];
    const float* Wk = (const float*)d_in[3];
    const float* bk = (const float*)d_in[4];
    const float* Wv = (const float*)d_in[5];
    const float* bv = (const float*)d_in[6];
    const float* Wo = (const float*)d_in[7];
    const float* bo = (const float*)d_in[8];
    const int*   mask = (const int*)d_in[9];
    float* out = (float*)d_out;

    cudaFuncSetAttribute(flash_kernel, cudaFuncAttributeMaxDynamicSharedMemorySize,
                         FLASH_SMEM);

    compact_kernel<<<1, 1024>>>(mask);
    qkv_kernel<<<dim3(HDIM / 128, SEQ / 128, 3), 256>>>(x, Wq, bq, Wk, bk, Wv, bv);
    gather_kernel<<<dim3(SEQ / 8, NHEAD), 256>>>();
    flash_kernel<<<dim3(SEQ / 64, NHEAD), 128, FLASH_SMEM>>>();
    oproj_kernel<<<dim3(HDIM / 128, SEQ / 128), 256>>>(Wo, bo, out);
}

// round 5
// speedup vs baseline: 3.9295x; 1.1991x over previous
#include <cuda_runtime.h>
#include <math.h>
#include <stdint.h>

#define SEQ  4096
#define HDIM 768
#define NHEAD 12
#define HD   64

// Scratch
__device__ float g_q[NHEAD * SEQ * HD];
__device__ float g_k[NHEAD * SEQ * HD];
__device__ float g_v[NHEAD * SEQ * HD];
__device__ float g_k2[NHEAD * SEQ * HD];   // compacted K
__device__ float g_v2[NHEAD * SEQ * HD];   // compacted V
__device__ float g_ctx[NHEAD * SEQ * HD];
__device__ int   g_kidx[SEQ];
__device__ int   g_cnt;

__device__ __forceinline__ uint32_t f2tf(float f) {
    uint32_t u;
    asm("cvt.rna.tf32.f32 %0, %1;" : "=r"(u) : "f"(f));
    return u;
}

__device__ __forceinline__ void mma_tf32(float c[4],
                                         uint32_t a0, uint32_t a1, uint32_t a2, uint32_t a3,
                                         uint32_t b0, uint32_t b1) {
    asm volatile("mma.sync.aligned.m16n8k8.row.col.f32.tf32.tf32.f32 "
                 "{%0,%1,%2,%3}, {%4,%5,%6,%7}, {%8,%9}, {%0,%1,%2,%3};"
                 : "+f"(c[0]), "+f"(c[1]), "+f"(c[2]), "+f"(c[3])
                 : "r"(a0), "r"(a1), "r"(a2), "r"(a3), "r"(b0), "r"(b1));
}

// ---------------------------------------------------------------------------
// Compaction: stable scan of unmasked column indices (mask==0 keeps)
// ---------------------------------------------------------------------------
__global__ void compact_kernel(const int* __restrict__ mask) {
    __shared__ int wsum[32];
    int tid = threadIdx.x, lane = tid & 31, wid = tid >> 5;
    int f[4];
    int c = 0;
    #pragma unroll
    for (int r = 0; r < 4; r++) {
        f[r] = (mask[tid * 4 + r] == 0) ? 1 : 0;
        c += f[r];
    }
    int inc = c;
    #pragma unroll
    for (int o = 1; o < 32; o <<= 1) {
        int n = __shfl_up_sync(0xffffffffu, inc, o);
        if (lane >= o) inc += n;
    }
    if (lane == 31) wsum[wid] = inc;
    __syncthreads();
    if (wid == 0) {
        int v = wsum[lane];
        int s = v;
        #pragma unroll
        for (int o = 1; o < 32; o <<= 1) {
            int n = __shfl_up_sync(0xffffffffu, s, o);
            if (lane >= o) s += n;
        }
        wsum[lane] = s - v;
        if (lane == 31) g_cnt = s;
    }
    __syncthreads();
    int base = wsum[wid] + inc - c;
    #pragma unroll
    for (int r = 0; r < 4; r++) {
        if (f[r]) g_kidx[base++] = tid * 4 + r;
    }
}

// ---------------------------------------------------------------------------
// Gather compacted K/V rows.
// ---------------------------------------------------------------------------
__global__ __launch_bounds__(256)
void gather_kernel() {
    int h = blockIdx.y;
    int jr = blockIdx.x * 8 + (threadIdx.x >> 5);
    int lane = threadIdx.x & 31;
    int cnt = g_cnt;
    if (jr >= cnt) return;
    int src = g_kidx[jr];
    const float2* ks = (const float2*)(g_k + ((size_t)h * SEQ + src) * HD);
    float2*       kd = (float2*)(g_k2 + ((size_t)h * SEQ + jr) * HD);
    kd[lane] = ks[lane];
    const float2* vs = (const float2*)(g_v + ((size_t)h * SEQ + src) * HD);
    float2*       vd = (float2*)(g_v2 + ((size_t)h * SEQ + jr) * HD);
    vd[lane] = vs[lane];
}

// ---------------------------------------------------------------------------
// tf32 mma GEMM (unchanged from R4): C = A @ W^T + bias, CTA 128x128, BK=16.
// ---------------------------------------------------------------------------
template<bool AHEAD, bool OHEAD>
__device__ __forceinline__ void gemm_body(const float* __restrict__ A,
                                          const float* __restrict__ W,
                                          const float* __restrict__ bias,
                                          float* __restrict__ dst,
                                          uint32_t* As, uint32_t* Bs) {
    int tid = threadIdx.x;
    int lane = tid & 31, warp = tid >> 5;
    int g = lane >> 2, tg = lane & 3;
    int warp_m = warp & 3, warp_n = warp >> 2;
    int mbase = blockIdx.y * 128, nbase = blockIdx.x * 128;

    int row0 = tid >> 2;
    int row1 = 64 + row0;
    int c4   = tid & 3;

    int aT0 = ((c4 >> 1) * 8 + (row0 >> 4)) * 128 + (row0 & 7) * 16 + ((row0 >> 3) & 1) + 2 * (c4 & 1);
    int aT1 = ((c4 >> 1) * 8 + (row1 >> 4)) * 128 + (row1 & 7) * 16 + ((row1 >> 3) & 1) + 2 * (c4 & 1);
    int bT0 = ((c4 >> 1) * 8 + (row0 >> 4)) * 128 + (row0 & 7) * 16 + (c4 & 1) + 2 * ((row0 >> 3) & 1);
    int bT1 = ((c4 >> 1) * 8 + (row1 >> 4)) * 128 + (row1 & 7) * 16 + (c4 & 1) + 2 * ((row1 >> 3) & 1);

    auto ldA = [&](int row, int kb) -> float4 {
        int kg = kb + c4 * 4;
        if (AHEAD)
            return *(const float4*)(A + (((size_t)(kg >> 6)) * SEQ + (mbase + row)) * HD + (kg & 63));
        else
            return *(const float4*)(A + (size_t)(mbase + row) * HDIM + kg);
    };
    auto ldW = [&](int row, int kb) -> float4 {
        return *(const float4*)(W + (size_t)(nbase + row) * HDIM + kb + c4 * 4);
    };
    auto stsv = [&](uint32_t* buf, int base, float4 v) {
        buf[base]      = f2tf(v.x);
        buf[base + 4]  = f2tf(v.y);
        buf[base + 8]  = f2tf(v.z);
        buf[base + 12] = f2tf(v.w);
    };

    float4 ra0 = ldA(row0, 0), ra1 = ldA(row1, 0);
    float4 rb0 = ldW(row0, 0), rb1 = ldW(row1, 0);
    stsv(As, aT0, ra0); stsv(As, aT1, ra1);
    stsv(Bs, bT0, rb0); stsv(Bs, bT1, rb1);
    __syncthreads();

    float acc[2][8][4] = {};

    const int NST = HDIM / 16;
    for (int s = 0; s < NST; s++) {
        int buf = (s & 1) * 2048;
        bool more = (s + 1 < NST);
        if (more) {
            int kb = (s + 1) * 16;
            ra0 = ldA(row0, kb); ra1 = ldA(row1, kb);
            rb0 = ldW(row0, kb); rb1 = ldW(row1, kb);
        }
        #pragma unroll
        for (int ks = 0; ks < 2; ks++) {
            uint4 a0 = *(uint4*)&As[buf + (ks * 8 + warp_m * 2 + 0) * 128 + lane * 4];
            uint4 a1 = *(uint4*)&As[buf + (ks * 8 + warp_m * 2 + 1) * 128 + lane * 4];
            uint4 b0 = *(uint4*)&Bs[buf + (ks * 8 + warp_n * 4 + 0) * 128 + lane * 4];
            uint4 b1 = *(uint4*)&Bs[buf + (ks * 8 + warp_n * 4 + 1) * 128 + lane * 4];
            uint4 b2 = *(uint4*)&Bs[buf + (ks * 8 + warp_n * 4 + 2) * 128 + lane * 4];
            uint4 b3 = *(uint4*)&Bs[buf + (ks * 8 + warp_n * 4 + 3) * 128 + lane * 4];
            mma_tf32(acc[0][0], a0.x, a0.y, a0.z, a0.w, b0.x, b0.y);
            mma_tf32(acc[0][1], a0.x, a0.y, a0.z, a0.w, b0.z, b0.w);
            mma_tf32(acc[0][2], a0.x, a0.y, a0.z, a0.w, b1.x, b1.y);
            mma_tf32(acc[0][3], a0.x, a0.y, a0.z, a0.w, b1.z, b1.w);
            mma_tf32(acc[0][4], a0.x, a0.y, a0.z, a0.w, b2.x, b2.y);
            mma_tf32(acc[0][5], a0.x, a0.y, a0.z, a0.w, b2.z, b2.w);
            mma_tf32(acc[0][6], a0.x, a0.y, a0.z, a0.w, b3.x, b3.y);
            mma_tf32(acc[0][7], a0.x, a0.y, a0.z, a0.w, b3.z, b3.w);
            mma_tf32(acc[1][0], a1.x, a1.y, a1.z, a1.w, b0.x, b0.y);
            mma_tf32(acc[1][1], a1.x, a1.y, a1.z, a1.w, b0.z, b0.w);
            mma_tf32(acc[1][2], a1.x, a1.y, a1.z, a1.w, b1.x, b1.y);
            mma_tf32(acc[1][3], a1.x, a1.y, a1.z, a1.w, b1.z, b1.w);
            mma_tf32(acc[1][4], a1.x, a1.y, a1.z, a1.w, b2.x, b2.y);
            mma_tf32(acc[1][5], a1.x, a1.y, a1.z, a1.w, b2.z, b2.w);
            mma_tf32(acc[1][6], a1.x, a1.y, a1.z, a1.w, b3.x, b3.y);
            mma_tf32(acc[1][7], a1.x, a1.y, a1.z, a1.w, b3.z, b3.w);
        }
        __syncthreads();
        if (more) {
            int nb = ((s + 1) & 1) * 2048;
            stsv(As + nb, aT0, ra0); stsv(As + nb, aT1, ra1);
            stsv(Bs + nb, bT0, rb0); stsv(Bs + nb, bT1, rb1);
        }
        __syncthreads();
    }

    #pragma unroll
    for (int i = 0; i < 2; i++) {
        int m0 = mbase + warp_m * 32 + i * 16 + g;
        #pragma unroll
        for (int nt = 0; nt < 8; nt++) {
            int n0 = nbase + warp_n * 64 + nt * 8 + 2 * tg;
            float bx = bias[n0], by = bias[n0 + 1];
            float2 v0 = make_float2(acc[i][nt][0] + bx, acc[i][nt][1] + by);
            float2 v1 = make_float2(acc[i][nt][2] + bx, acc[i][nt][3] + by);
            if (OHEAD) {
                float* p = dst + (((size_t)(n0 >> 6)) * SEQ + m0) * HD + (n0 & 63);
                *(float2*)p = v0;
                *(float2*)(p + 8 * HD) = v1;
            } else {
                *(float2*)(dst + (size_t)m0 * HDIM + n0) = v0;
                *(float2*)(dst + (size_t)(m0 + 8) * HDIM + n0) = v1;
            }
        }
    }
}

__global__ __launch_bounds__(256)
void qkv_kernel(const float* __restrict__ x,
                const float* __restrict__ Wq, const float* __restrict__ bq,
                const float* __restrict__ Wk, const float* __restrict__ bk,
                const float* __restrict__ Wv, const float* __restrict__ bv) {
    __shared__ __align__(16) uint32_t As[4096];
    __shared__ __align__(16) uint32_t Bs[4096];
    const float *W, *bias;
    float* dst;
    int z = blockIdx.z;
    if (z == 0)      { W = Wq; bias = bq; dst = g_q; }
    else if (z == 1) { W = Wk; bias = bk; dst = g_k; }
    else             { W = Wv; bias = bv; dst = g_v; }
    gemm_body<false, true>(x, W, bias, dst, As, Bs);
}

__global__ __launch_bounds__(256)
void oproj_kernel(const float* __restrict__ Wo, const float* __restrict__ bo,
                  float* __restrict__ out) {
    __shared__ __align__(16) uint32_t As[4096];
    __shared__ __align__(16) uint32_t Bs[4096];
    gemm_body<true, false>(g_ctx, Wo, bo, out, As, Bs);
}

// ---------------------------------------------------------------------------
// Flash attention. CTA = (head, 128 q rows), 128 thr = 4 warps x m32.
// Q fragments register-resident (16 uint4); K/V/P permuted smem, all LDS.128.
// Smem: Qp 64 tiles (32KB) | Kp 32 (16KB) | Vp 32 (16KB) | Pp 4x16 (32KB)
// ---------------------------------------------------------------------------
#define FLASH_SMEM (24576 * 4)

__global__ __launch_bounds__(128)
void flash_kernel() {
    extern __shared__ uint32_t sm[];
    uint32_t* Qp = sm;             // tiles (ks*8 + mt), mt=0..7
    uint32_t* Kp = sm + 8192;      // tiles (ks*4 + np)
    uint32_t* Vp = sm + 12288;     // tiles (ksj*4 + np)
    uint32_t* Pp = sm + 16384;     // per-warp 16 tiles (ksj*2 + mtl)

    int tid = threadIdx.x;
    int lane = tid & 31, warp = tid >> 5;
    int g = lane >> 2, tg = lane & 3;
    int h = blockIdx.y, qb = blockIdx.x * 128;
    int cnt = g_cnt;

    // Q -> permuted smem (A layout), 128 rows
    const float* Qg = g_q + ((size_t)h * SEQ + qb) * HD;
    #pragma unroll
    for (int r = 0; r < 16; r++) {
        int idx = r * 128 + tid;
        int row = idx >> 4, c4 = idx & 15;
        float4 v = *(const float4*)(Qg + (size_t)row * HD + c4 * 4);
        int base = ((c4 >> 1) * 8 + (row >> 4)) * 128 + (row & 7) * 16
                 + ((row >> 3) & 1) + 2 * (c4 & 1);
        Qp[base]      = f2tf(v.x);
        Qp[base + 4]  = f2tf(v.y);
        Qp[base + 8]  = f2tf(v.z);
        Qp[base + 12] = f2tf(v.w);
    }
    __syncthreads();
    uint4 q[8][2];
    #pragma unroll
    for (int ks = 0; ks < 8; ks++)
        #pragma unroll
        for (int mtl = 0; mtl < 2; mtl++)
            q[ks][mtl] = *(uint4*)&Qp[(ks * 8 + warp * 2 + mtl) * 128 + lane * 4];

    float m[2][2] = {{-1e30f, -1e30f}, {-1e30f, -1e30f}};
    float l[2][2] = {{0.f, 0.f}, {0.f, 0.f}};
    float acc[2][8][4] = {};

    const float* Kg = g_k2 + (size_t)h * SEQ * HD;
    const float* Vg = g_v2 + (size_t)h * SEQ * HD;
    int ntile = (cnt + 63) >> 6;

    int t2a = (2 * tg) & 3,     s2a = ((2 * tg) >> 2) * 2;
    int t2b = (2 * tg + 1) & 3, s2b = ((2 * tg + 1) >> 2) * 2;
    int pw = warp * 2048;

    for (int t = 0; t < ntile; t++) {
        int kvb = t * 64;
        __syncthreads();
        // K (B layout over d) and V (B layout over j) producers
        #pragma unroll
        for (int r = 0; r < 8; r++) {
            int idx = r * 128 + tid;
            int row = idx >> 4, c4 = idx & 15;
            bool ok = (kvb + row) < cnt;
            float4 kv = ok ? *(const float4*)(Kg + (size_t)(kvb + row) * HD + c4 * 4)
                           : make_float4(0.f, 0.f, 0.f, 0.f);
            int kb2 = ((c4 >> 1) * 4 + (row >> 4)) * 128 + (row & 7) * 16
                    + (c4 & 1) + 2 * ((row >> 3) & 1);
            Kp[kb2]      = f2tf(kv.x);
            Kp[kb2 + 4]  = f2tf(kv.y);
            Kp[kb2 + 8]  = f2tf(kv.z);
            Kp[kb2 + 12] = f2tf(kv.w);
            float4 vv = ok ? *(const float4*)(Vg + (size_t)(kvb + row) * HD + c4 * 4)
                           : make_float4(0.f, 0.f, 0.f, 0.f);
            int vb2 = ((row >> 3) * 4 + (c4 >> 2)) * 128 + (row & 3) * 4
                    + ((row >> 2) & 1) + 2 * ((c4 >> 1) & 1);
            int gg = (c4 & 1) * 4;
            Vp[vb2 + (gg + 0) * 16] = f2tf(vv.x);
            Vp[vb2 + (gg + 1) * 16] = f2tf(vv.y);
            Vp[vb2 + (gg + 2) * 16] = f2tf(vv.z);
            Vp[vb2 + (gg + 3) * 16] = f2tf(vv.w);
        }
        __syncthreads();

        // S = Q K^T  (warp: 32x64)
        float sc[2][8][4] = {};
        #pragma unroll
        for (int ks = 0; ks < 8; ks++) {
            uint4 b0 = *(uint4*)&Kp[(ks * 4 + 0) * 128 + lane * 4];
            uint4 b1 = *(uint4*)&Kp[(ks * 4 + 1) * 128 + lane * 4];
            uint4 b2 = *(uint4*)&Kp[(ks * 4 + 2) * 128 + lane * 4];
            uint4 b3 = *(uint4*)&Kp[(ks * 4 + 3) * 128 + lane * 4];
            #pragma unroll
            for (int mtl = 0; mtl < 2; mtl++) {
                uint4 a = q[ks][mtl];
                mma_tf32(sc[mtl][0], a.x, a.y, a.z, a.w, b0.x, b0.y);
                mma_tf32(sc[mtl][1], a.x, a.y, a.z, a.w, b0.z, b0.w);
                mma_tf32(sc[mtl][2], a.x, a.y, a.z, a.w, b1.x, b1.y);
                mma_tf32(sc[mtl][3], a.x, a.y, a.z, a.w, b1.z, b1.w);
                mma_tf32(sc[mtl][4], a.x, a.y, a.z, a.w, b2.x, b2.y);
                mma_tf32(sc[mtl][5], a.x, a.y, a.z, a.w, b2.z, b2.w);
                mma_tf32(sc[mtl][6], a.x, a.y, a.z, a.w, b3.x, b3.y);
                mma_tf32(sc[mtl][7], a.x, a.y, a.z, a.w, b3.z, b3.w);
            }
        }

        bool tail = (kvb + 64 > cnt);

        #pragma unroll
        for (int mtl = 0; mtl < 2; mtl++) {
            // scale + tail mask
            #pragma unroll
            for (int nt = 0; nt < 8; nt++) {
                #pragma unroll
                for (int e = 0; e < 4; e++)
                    sc[mtl][nt][e] *= 0.125f;
            }
            if (tail) {
                #pragma unroll
                for (int nt = 0; nt < 8; nt++) {
                    int c0 = kvb + nt * 8 + 2 * tg;
                    if (c0     >= cnt) { sc[mtl][nt][0] = -1e30f; sc[mtl][nt][2] = -1e30f; }
                    if (c0 + 1 >= cnt) { sc[mtl][nt][1] = -1e30f; sc[mtl][nt][3] = -1e30f; }
                }
            }

            // online softmax for rows g / g+8 of this mtl
            float rm0 = -1e30f, rm1 = -1e30f;
            #pragma unroll
            for (int nt = 0; nt < 8; nt++) {
                rm0 = fmaxf(rm0, fmaxf(sc[mtl][nt][0], sc[mtl][nt][1]));
                rm1 = fmaxf(rm1, fmaxf(sc[mtl][nt][2], sc[mtl][nt][3]));
            }
            rm0 = fmaxf(rm0, __shfl_xor_sync(0xffffffffu, rm0, 1));
            rm0 = fmaxf(rm0, __shfl_xor_sync(0xffffffffu, rm0, 2));
            rm1 = fmaxf(rm1, __shfl_xor_sync(0xffffffffu, rm1, 1));
            rm1 = fmaxf(rm1, __shfl_xor_sync(0xffffffffu, rm1, 2));

            float mn0 = fmaxf(m[mtl][0], rm0), mn1 = fmaxf(m[mtl][1], rm1);
            float al0 = __expf(m[mtl][0] - mn0), al1 = __expf(m[mtl][1] - mn1);
            float rs0 = 0.f, rs1 = 0.f;
            #pragma unroll
            for (int nt = 0; nt < 8; nt++) {
                float p0 = __expf(sc[mtl][nt][0] - mn0); sc[mtl][nt][0] = p0; rs0 += p0;
                float p1 = __expf(sc[mtl][nt][1] - mn0); sc[mtl][nt][1] = p1; rs0 += p1;
                float p2 = __expf(sc[mtl][nt][2] - mn1); sc[mtl][nt][2] = p2; rs1 += p2;
                float p3 = __expf(sc[mtl][nt][3] - mn1); sc[mtl][nt][3] = p3; rs1 += p3;
            }
            rs0 += __shfl_xor_sync(0xffffffffu, rs0, 1);
            rs0 += __shfl_xor_sync(0xffffffffu, rs0, 2);
            rs1 += __shfl_xor_sync(0xffffffffu, rs1, 1);
            rs1 += __shfl_xor_sync(0xffffffffu, rs1, 2);
            l[mtl][0] = l[mtl][0] * al0 + rs0; m[mtl][0] = mn0;
            l[mtl][1] = l[mtl][1] * al1 + rs1; m[mtl][1] = mn1;
            #pragma unroll
            for (int nt = 0; nt < 8; nt++) {
                acc[mtl][nt][0] *= al0; acc[mtl][nt][1] *= al0;
                acc[mtl][nt][2] *= al1; acc[mtl][nt][3] *= al1;
            }

            // P -> permuted A layout, tile (nt*2 + mtl)
            int pb = pw + mtl * 128 + g * 16;
            #pragma unroll
            for (int nt = 0; nt < 8; nt++) {
                int bb = pb + nt * 256;
                Pp[bb + t2a * 4 + s2a]     = f2tf(sc[mtl][nt][0]);
                Pp[bb + t2b * 4 + s2b]     = f2tf(sc[mtl][nt][1]);
                Pp[bb + t2a * 4 + s2a + 1] = f2tf(sc[mtl][nt][2]);
                Pp[bb + t2b * 4 + s2b + 1] = f2tf(sc[mtl][nt][3]);
            }
        }
        __syncwarp();

        // acc += P @ V
        #pragma unroll
        for (int ks = 0; ks < 8; ks++) {
            uint4 pa0 = *(uint4*)&Pp[pw + (ks * 2 + 0) * 128 + lane * 4];
            uint4 pa1 = *(uint4*)&Pp[pw + (ks * 2 + 1) * 128 + lane * 4];
            uint4 b0 = *(uint4*)&Vp[(ks * 4 + 0) * 128 + lane * 4];
            uint4 b1 = *(uint4*)&Vp[(ks * 4 + 1) * 128 + lane * 4];
            uint4 b2 = *(uint4*)&Vp[(ks * 4 + 2) * 128 + lane * 4];
            uint4 b3 = *(uint4*)&Vp[(ks * 4 + 3) * 128 + lane * 4];
            mma_tf32(acc[0][0], pa0.x, pa0.y, pa0.z, pa0.w, b0.x, b0.y);
            mma_tf32(acc[0][1], pa0.x, pa0.y, pa0.z, pa0.w, b0.z, b0.w);
            mma_tf32(acc[0][2], pa0.x, pa0.y, pa0.z, pa0.w, b1.x, b1.y);
            mma_tf32(acc[0][3], pa0.x, pa0.y, pa0.z, pa0.w, b1.z, b1.w);
            mma_tf32(acc[0][4], pa0.x, pa0.y, pa0.z, pa0.w, b2.x, b2.y);
            mma_tf32(acc[0][5], pa0.x, pa0.y, pa0.z, pa0.w, b2.z, b2.w);
            mma_tf32(acc[0][6], pa0.x, pa0.y, pa0.z, pa0.w, b3.x, b3.y);
            mma_tf32(acc[0][7], pa0.x, pa0.y, pa0.z, pa0.w, b3.z, b3.w);
            mma_tf32(acc[1][0], pa1.x, pa1.y, pa1.z, pa1.w, b0.x, b0.y);
            mma_tf32(acc[1][1], pa1.x, pa1.y, pa1.z, pa1.w, b0.z, b0.w);
            mma_tf32(acc[1][2], pa1.x, pa1.y, pa1.z, pa1.w, b1.x, b1.y);
            mma_tf32(acc[1][3], pa1.x, pa1.y, pa1.z, pa1.w, b1.z, b1.w);
            mma_tf32(acc[1][4], pa1.x, pa1.y, pa1.z, pa1.w, b2.x, b2.y);
            mma_tf32(acc[1][5], pa1.x, pa1.y, pa1.z, pa1.w, b2.z, b2.w);
            mma_tf32(acc[1][6], pa1.x, pa1.y, pa1.z, pa1.w, b3.x, b3.y);
            mma_tf32(acc[1][7], pa1.x, pa1.y, pa1.z, pa1.w, b3.z, b3.w);
        }
    }

    // epilogue
    #pragma unroll
    for (int mtl = 0; mtl < 2; mtl++) {
        float i0 = 1.0f / l[mtl][0], i1 = 1.0f / l[mtl][1];
        float* Og = g_ctx + ((size_t)h * SEQ + qb + warp * 32 + mtl * 16) * HD;
        #pragma unroll
        for (int nt = 0; nt < 8; nt++) {
            int col = nt * 8 + 2 * tg;
            *(float2*)&Og[(size_t)g * HD + col] =
                make_float2(acc[mtl][nt][0] * i0, acc[mtl][nt][1] * i0);
            *(float2*)&Og[(size_t)(g + 8) * HD + col] =
                make_float2(acc[mtl][nt][2] * i1, acc[mtl][nt][3] * i1);
        }
    }
}

// ---------------------------------------------------------------------------
extern "C" void kernel_launch(void* const* d_in, const int* in_sizes, int n_in,
                              void* d_out, int out_size) {
    const float* x  = (const float*)d_in[0];
    const float* Wq = (const float*)d_in[1];
    const float* bq = (const float*)d_in[2];
    const float* Wk = (const float*)d_in[3];
    const float* bk = (const float*)d_in[4];
    const float* Wv = (const float*)d_in[5];
    const float* bv = (const float*)d_in[6];
    const float* Wo = (const float*)d_in[7];
    const float* bo = (const float*)d_in[8];
    const int*   mask = (const int*)d_in[9];
    float* out = (float*)d_out;

    cudaFuncSetAttribute(flash_kernel, cudaFuncAttributeMaxDynamicSharedMemorySize,
                         FLASH_SMEM);

    compact_kernel<<<1, 1024>>>(mask);
    qkv_kernel<<<dim3(HDIM / 128, SEQ / 128, 3), 256>>>(x, Wq, bq, Wk, bk, Wv, bv);
    gather_kernel<<<dim3(SEQ / 8, NHEAD), 256>>>();
    flash_kernel<<<dim3(SEQ / 128, NHEAD), 128, FLASH_SMEM>>>();
    oproj_kernel<<<dim3(HDIM / 128, SEQ / 128), 256>>>(Wo, bo, out);
}

// round 6
// speedup vs baseline: 4.8250x; 1.2279x over previous
#include <cuda_runtime.h>
#include <math.h>
#include <stdint.h>

#define SEQ  4096
#define HDIM 768
#define NHEAD 12
#define HD   64

// Scratch
__device__ float g_q[NHEAD * SEQ * HD];
__device__ float g_k[NHEAD * SEQ * HD];
__device__ float g_v[NHEAD * SEQ * HD];
__device__ float g_k2[NHEAD * SEQ * HD];   // K, fragment-permuted tf32
__device__ float g_v2[NHEAD * SEQ * HD];   // V, fragment-permuted tf32
__device__ float g_ctx[NHEAD * SEQ * HD];
__device__ int   g_kidx[SEQ];
__device__ int   g_cnt;

__device__ __forceinline__ uint32_t f2tf(float f) {
    uint32_t u;
    asm("cvt.rna.tf32.f32 %0, %1;" : "=r"(u) : "f"(f));
    return u;
}

__device__ __forceinline__ void mma_tf32(float c[4],
                                         uint32_t a0, uint32_t a1, uint32_t a2, uint32_t a3,
                                         uint32_t b0, uint32_t b1) {
    asm volatile("mma.sync.aligned.m16n8k8.row.col.f32.tf32.tf32.f32 "
                 "{%0,%1,%2,%3}, {%4,%5,%6,%7}, {%8,%9}, {%0,%1,%2,%3};"
                 : "+f"(c[0]), "+f"(c[1]), "+f"(c[2]), "+f"(c[3])
                 : "r"(a0), "r"(a1), "r"(a2), "r"(a3), "r"(b0), "r"(b1));
}

__device__ __forceinline__ void cp16(uint32_t smem_addr, const void* gptr) {
    asm volatile("cp.async.cg.shared.global [%0], [%1], 16;"
                 :: "r"(smem_addr), "l"(gptr));
}
#define CP_COMMIT() asm volatile("cp.async.commit_group;")
#define CP_WAIT1()  asm volatile("cp.async.wait_group 1;")

// ---------------------------------------------------------------------------
// Compaction: stable scan of unmasked column indices (mask==0 keeps)
// ---------------------------------------------------------------------------
__global__ void compact_kernel(const int* __restrict__ mask) {
    __shared__ int wsum[32];
    int tid = threadIdx.x, lane = tid & 31, wid = tid >> 5;
    int f[4];
    int c = 0;
    #pragma unroll
    for (int r = 0; r < 4; r++) {
        f[r] = (mask[tid * 4 + r] == 0) ? 1 : 0;
        c += f[r];
    }
    int inc = c;
    #pragma unroll
    for (int o = 1; o < 32; o <<= 1) {
        int n = __shfl_up_sync(0xffffffffu, inc, o);
        if (lane >= o) inc += n;
    }
    if (lane == 31) wsum[wid] = inc;
    __syncthreads();
    if (wid == 0) {
        int v = wsum[lane];
        int s = v;
        #pragma unroll
        for (int o = 1; o < 32; o <<= 1) {
            int n = __shfl_up_sync(0xffffffffu, s, o);
            if (lane >= o) s += n;
        }
        wsum[lane] = s - v;
        if (lane == 31) g_cnt = s;
    }
    __syncthreads();
    int base = wsum[wid] + inc - c;
    #pragma unroll
    for (int r = 0; r < 4; r++) {
        if (f[r]) g_kidx[base++] = tid * 4 + r;
    }
}

// ---------------------------------------------------------------------------
// Gather + fragment-permute + tf32 convert K/V into g_k2/g_v2.
// Layout per head: [T=64 kv-tiles][32 subtiles][128 words].
// K subtile (ks*4+np): word(l,s): d = ks*8+(s&1)*4+(l&3), j = np*16+(s>>1)*8+(l>>2)
// V subtile (kj*4+np): word(l,s): j = kj*8+(s&1)*4+(l&3), d = np*16+(s>>1)*8+(l>>2)
// grid (64, NHEAD), block 128.
// ---------------------------------------------------------------------------
__global__ __launch_bounds__(128)
void gather_permute_kernel() {
    int h = blockIdx.y;
    int T = blockIdx.x;
    int cnt = g_cnt;
    if (T * 64 >= cnt) return;
    int tid = threadIdx.x;
    int lane = tid & 31, warp = tid >> 5;
    const float* Kh = g_k + (size_t)h * SEQ * HD;
    const float* Vh = g_v + (size_t)h * SEQ * HD;
    uint32_t* dstK = (uint32_t*)g_k2 + ((size_t)h * 64 + T) * 4096;
    uint32_t* dstV = (uint32_t*)g_v2 + ((size_t)h * 64 + T) * 4096;
    int jb = T * 64;
    #pragma unroll
    for (int i = 0; i < 8; i++) {
        int st = warp * 8 + i;
        int hi = st >> 2, np = st & 3;
        {   // K
            uint32_t w[4];
            #pragma unroll
            for (int s = 0; s < 4; s++) {
                int d = hi * 8 + (s & 1) * 4 + (lane & 3);
                int j = jb + np * 16 + (s >> 1) * 8 + (lane >> 2);
                float v = (j < cnt) ? Kh[(size_t)g_kidx[j] * HD + d] : 0.0f;
                w[s] = f2tf(v);
            }
            *(uint4*)&dstK[st * 128 + lane * 4] = *(uint4*)w;
        }
        {   // V
            uint32_t w[4];
            #pragma unroll
            for (int s = 0; s < 4; s++) {
                int j = jb + hi * 8 + (s & 1) * 4 + (lane & 3);
                int d = np * 16 + (s >> 1) * 8 + (lane >> 2);
                float v = (j < cnt) ? Vh[(size_t)g_kidx[j] * HD + d] : 0.0f;
                w[s] = f2tf(v);
            }
            *(uint4*)&dstV[st * 128 + lane * 4] = *(uint4*)w;
        }
    }
}

// ---------------------------------------------------------------------------
// tf32 mma GEMM (unchanged): C = A @ W^T + bias, CTA 128x128, BK=16.
// ---------------------------------------------------------------------------
template<bool AHEAD, bool OHEAD>
__device__ __forceinline__ void gemm_body(const float* __restrict__ A,
                                          const float* __restrict__ W,
                                          const float* __restrict__ bias,
                                          float* __restrict__ dst,
                                          uint32_t* As, uint32_t* Bs) {
    int tid = threadIdx.x;
    int lane = tid & 31, warp = tid >> 5;
    int g = lane >> 2, tg = lane & 3;
    int warp_m = warp & 3, warp_n = warp >> 2;
    int mbase = blockIdx.y * 128, nbase = blockIdx.x * 128;

    int row0 = tid >> 2;
    int row1 = 64 + row0;
    int c4   = tid & 3;

    int aT0 = ((c4 >> 1) * 8 + (row0 >> 4)) * 128 + (row0 & 7) * 16 + ((row0 >> 3) & 1) + 2 * (c4 & 1);
    int aT1 = ((c4 >> 1) * 8 + (row1 >> 4)) * 128 + (row1 & 7) * 16 + ((row1 >> 3) & 1) + 2 * (c4 & 1);
    int bT0 = ((c4 >> 1) * 8 + (row0 >> 4)) * 128 + (row0 & 7) * 16 + (c4 & 1) + 2 * ((row0 >> 3) & 1);
    int bT1 = ((c4 >> 1) * 8 + (row1 >> 4)) * 128 + (row1 & 7) * 16 + (c4 & 1) + 2 * ((row1 >> 3) & 1);

    auto ldA = [&](int row, int kb) -> float4 {
        int kg = kb + c4 * 4;
        if (AHEAD)
            return *(const float4*)(A + (((size_t)(kg >> 6)) * SEQ + (mbase + row)) * HD + (kg & 63));
        else
            return *(const float4*)(A + (size_t)(mbase + row) * HDIM + kg);
    };
    auto ldW = [&](int row, int kb) -> float4 {
        return *(const float4*)(W + (size_t)(nbase + row) * HDIM + kb + c4 * 4);
    };
    auto stsv = [&](uint32_t* buf, int base, float4 v) {
        buf[base]      = f2tf(v.x);
        buf[base + 4]  = f2tf(v.y);
        buf[base + 8]  = f2tf(v.z);
        buf[base + 12] = f2tf(v.w);
    };

    float4 ra0 = ldA(row0, 0), ra1 = ldA(row1, 0);
    float4 rb0 = ldW(row0, 0), rb1 = ldW(row1, 0);
    stsv(As, aT0, ra0); stsv(As, aT1, ra1);
    stsv(Bs, bT0, rb0); stsv(Bs, bT1, rb1);
    __syncthreads();

    float acc[2][8][4] = {};

    const int NST = HDIM / 16;
    for (int s = 0; s < NST; s++) {
        int buf = (s & 1) * 2048;
        bool more = (s + 1 < NST);
        if (more) {
            int kb = (s + 1) * 16;
            ra0 = ldA(row0, kb); ra1 = ldA(row1, kb);
            rb0 = ldW(row0, kb); rb1 = ldW(row1, kb);
        }
        #pragma unroll
        for (int ks = 0; ks < 2; ks++) {
            uint4 a0 = *(uint4*)&As[buf + (ks * 8 + warp_m * 2 + 0) * 128 + lane * 4];
            uint4 a1 = *(uint4*)&As[buf + (ks * 8 + warp_m * 2 + 1) * 128 + lane * 4];
            uint4 b0 = *(uint4*)&Bs[buf + (ks * 8 + warp_n * 4 + 0) * 128 + lane * 4];
            uint4 b1 = *(uint4*)&Bs[buf + (ks * 8 + warp_n * 4 + 1) * 128 + lane * 4];
            uint4 b2 = *(uint4*)&Bs[buf + (ks * 8 + warp_n * 4 + 2) * 128 + lane * 4];
            uint4 b3 = *(uint4*)&Bs[buf + (ks * 8 + warp_n * 4 + 3) * 128 + lane * 4];
            mma_tf32(acc[0][0], a0.x, a0.y, a0.z, a0.w, b0.x, b0.y);
            mma_tf32(acc[0][1], a0.x, a0.y, a0.z, a0.w, b0.z, b0.w);
            mma_tf32(acc[0][2], a0.x, a0.y, a0.z, a0.w, b1.x, b1.y);
            mma_tf32(acc[0][3], a0.x, a0.y, a0.z, a0.w, b1.z, b1.w);
            mma_tf32(acc[0][4], a0.x, a0.y, a0.z, a0.w, b2.x, b2.y);
            mma_tf32(acc[0][5], a0.x, a0.y, a0.z, a0.w, b2.z, b2.w);
            mma_tf32(acc[0][6], a0.x, a0.y, a0.z, a0.w, b3.x, b3.y);
            mma_tf32(acc[0][7], a0.x, a0.y, a0.z, a0.w, b3.z, b3.w);
            mma_tf32(acc[1][0], a1.x, a1.y, a1.z, a1.w, b0.x, b0.y);
            mma_tf32(acc[1][1], a1.x, a1.y, a1.z, a1.w, b0.z, b0.w);
            mma_tf32(acc[1][2], a1.x, a1.y, a1.z, a1.w, b1.x, b1.y);
            mma_tf32(acc[1][3], a1.x, a1.y, a1.z, a1.w, b1.z, b1.w);
            mma_tf32(acc[1][4], a1.x, a1.y, a1.z, a1.w, b2.x, b2.y);
            mma_tf32(acc[1][5], a1.x, a1.y, a1.z, a1.w, b2.z, b2.w);
            mma_tf32(acc[1][6], a1.x, a1.y, a1.z, a1.w, b3.x, b3.y);
            mma_tf32(acc[1][7], a1.x, a1.y, a1.z, a1.w, b3.z, b3.w);
        }
        __syncthreads();
        if (more) {
            int nb = ((s + 1) & 1) * 2048;
            stsv(As + nb, aT0, ra0); stsv(As + nb, aT1, ra1);
            stsv(Bs + nb, bT0, rb0); stsv(Bs + nb, bT1, rb1);
        }
        __syncthreads();
    }

    #pragma unroll
    for (int i = 0; i < 2; i++) {
        int m0 = mbase + warp_m * 32 + i * 16 + g;
        #pragma unroll
        for (int nt = 0; nt < 8; nt++) {
            int n0 = nbase + warp_n * 64 + nt * 8 + 2 * tg;
            float bx = bias[n0], by = bias[n0 + 1];
            float2 v0 = make_float2(acc[i][nt][0] + bx, acc[i][nt][1] + by);
            float2 v1 = make_float2(acc[i][nt][2] + bx, acc[i][nt][3] + by);
            if (OHEAD) {
                float* p = dst + (((size_t)(n0 >> 6)) * SEQ + m0) * HD + (n0 & 63);
                *(float2*)p = v0;
                *(float2*)(p + 8 * HD) = v1;
            } else {
                *(float2*)(dst + (size_t)m0 * HDIM + n0) = v0;
                *(float2*)(dst + (size_t)(m0 + 8) * HDIM + n0) = v1;
            }
        }
    }
}

__global__ __launch_bounds__(256)
void qkv_kernel(const float* __restrict__ x,
                const float* __restrict__ Wq, const float* __restrict__ bq,
                const float* __restrict__ Wk, const float* __restrict__ bk,
                const float* __restrict__ Wv, const float* __restrict__ bv) {
    __shared__ __align__(16) uint32_t As[4096];
    __shared__ __align__(16) uint32_t Bs[4096];
    const float *W, *bias;
    float* dst;
    int z = blockIdx.z;
    if (z == 0)      { W = Wq; bias = bq; dst = g_q; }
    else if (z == 1) { W = Wk; bias = bk; dst = g_k; }
    else             { W = Wv; bias = bv; dst = g_v; }
    gemm_body<false, true>(x, W, bias, dst, As, Bs);
}

__global__ __launch_bounds__(256)
void oproj_kernel(const float* __restrict__ Wo, const float* __restrict__ bo,
                  float* __restrict__ out) {
    __shared__ __align__(16) uint32_t As[4096];
    __shared__ __align__(16) uint32_t Bs[4096];
    gemm_body<true, false>(g_ctx, Wo, bo, out, As, Bs);
}

// ---------------------------------------------------------------------------
// Flash attention. CTA = (head, 128 q rows), 128 thr = 4 warps x m32.
// K/V arrive pre-permuted+tf32 from gather_permute; producer = cp.async
// 16B linear copies, double-buffered. Q staged once via Pp region.
// Smem: Kbuf0 16KB | Vbuf0 16KB | Kbuf1 16KB | Vbuf1 16KB | Pp/Qstage 32KB
// ---------------------------------------------------------------------------
#define FLASH_SMEM (24576 * 4)

__global__ __launch_bounds__(128)
void flash_kernel() {
    extern __shared__ uint32_t sm[];
    uint32_t* Pp = sm + 16384;

    int tid = threadIdx.x;
    int lane = tid & 31, warp = tid >> 5;
    int g = lane >> 2, tg = lane & 3;
    int h = blockIdx.y, qb = blockIdx.x * 128;
    int cnt = g_cnt;
    uint32_t smem_base = (uint32_t)__cvta_generic_to_shared(sm);

    // ---- Q staging (into Pp region) -> register fragments ----
    const float* Qg = g_q + ((size_t)h * SEQ + qb) * HD;
    #pragma unroll
    for (int r = 0; r < 16; r++) {
        int idx = r * 128 + tid;
        int row = idx >> 4, c4 = idx & 15;
        float4 v = *(const float4*)(Qg + (size_t)row * HD + c4 * 4);
        int base = ((c4 >> 1) * 8 + (row >> 4)) * 128 + (row & 7) * 16
                 + ((row >> 3) & 1) + 2 * (c4 & 1);
        Pp[base]      = f2tf(v.x);
        Pp[base + 4]  = f2tf(v.y);
        Pp[base + 8]  = f2tf(v.z);
        Pp[base + 12] = f2tf(v.w);
    }
    __syncthreads();
    uint4 q[8][2];
    #pragma unroll
    for (int ks = 0; ks < 8; ks++)
        #pragma unroll
        for (int mtl = 0; mtl < 2; mtl++)
            q[ks][mtl] = *(uint4*)&Pp[(ks * 8 + warp * 2 + mtl) * 128 + lane * 4];

    float m[2][2] = {{-1e30f, -1e30f}, {-1e30f, -1e30f}};
    float l[2][2] = {{0.f, 0.f}, {0.f, 0.f}};
    float acc[2][8][4] = {};

    const uint4* Ksrc = (const uint4*)((const uint32_t*)g_k2 + (size_t)h * 64 * 4096);
    const uint4* Vsrc = (const uint4*)((const uint32_t*)g_v2 + (size_t)h * 64 * 4096);
    int ntile = (cnt + 63) >> 6;

    int t2a = (2 * tg) & 3,     s2a = ((2 * tg) >> 2) * 2;
    int t2b = (2 * tg + 1) & 3, s2b = ((2 * tg + 1) >> 2) * 2;
    int pw = warp * 2048;

    auto prefetch = [&](int t, int buf) {
        uint32_t dk = smem_base + (uint32_t)(buf * 8192) * 4u;
        uint32_t dv = dk + 4096u * 4u;
        const uint4* sk = Ksrc + (size_t)t * 1024;
        const uint4* sv = Vsrc + (size_t)t * 1024;
        #pragma unroll
        for (int i = 0; i < 8; i++) {
            int o = i * 128 + tid;
            cp16(dk + (uint32_t)o * 16u, sk + o);
            cp16(dv + (uint32_t)o * 16u, sv + o);
        }
    };

    prefetch(0, 0);
    CP_COMMIT();

    for (int t = 0; t < ntile; t++) {
        int cur = t & 1;
        int kvb = t * 64;
        __syncthreads();                       // all warps done with buf cur^1
        if (t + 1 < ntile) prefetch(t + 1, cur ^ 1);
        CP_COMMIT();
        CP_WAIT1();                            // tile t resident (this thread)
        __syncthreads();                       // visibility across threads
        uint32_t* Kp = sm + cur * 8192;
        uint32_t* Vp = Kp + 4096;

        // S = Q K^T  (warp: 32x64)
        float sc[2][8][4] = {};
        #pragma unroll
        for (int ks = 0; ks < 8; ks++) {
            uint4 b0 = *(uint4*)&Kp[(ks * 4 + 0) * 128 + lane * 4];
            uint4 b1 = *(uint4*)&Kp[(ks * 4 + 1) * 128 + lane * 4];
            uint4 b2 = *(uint4*)&Kp[(ks * 4 + 2) * 128 + lane * 4];
            uint4 b3 = *(uint4*)&Kp[(ks * 4 + 3) * 128 + lane * 4];
            #pragma unroll
            for (int mtl = 0; mtl < 2; mtl++) {
                uint4 a = q[ks][mtl];
                mma_tf32(sc[mtl][0], a.x, a.y, a.z, a.w, b0.x, b0.y);
                mma_tf32(sc[mtl][1], a.x, a.y, a.z, a.w, b0.z, b0.w);
                mma_tf32(sc[mtl][2], a.x, a.y, a.z, a.w, b1.x, b1.y);
                mma_tf32(sc[mtl][3], a.x, a.y, a.z, a.w, b1.z, b1.w);
                mma_tf32(sc[mtl][4], a.x, a.y, a.z, a.w, b2.x, b2.y);
                mma_tf32(sc[mtl][5], a.x, a.y, a.z, a.w, b2.z, b2.w);
                mma_tf32(sc[mtl][6], a.x, a.y, a.z, a.w, b3.x, b3.y);
                mma_tf32(sc[mtl][7], a.x, a.y, a.z, a.w, b3.z, b3.w);
            }
        }

        bool tail = (kvb + 64 > cnt);

        #pragma unroll
        for (int mtl = 0; mtl < 2; mtl++) {
            #pragma unroll
            for (int nt = 0; nt < 8; nt++) {
                #pragma unroll
                for (int e = 0; e < 4; e++)
                    sc[mtl][nt][e] *= 0.125f;
            }
            if (tail) {
                #pragma unroll
                for (int nt = 0; nt < 8; nt++) {
                    int c0 = kvb + nt * 8 + 2 * tg;
                    if (c0     >= cnt) { sc[mtl][nt][0] = -1e30f; sc[mtl][nt][2] = -1e30f; }
                    if (c0 + 1 >= cnt) { sc[mtl][nt][1] = -1e30f; sc[mtl][nt][3] = -1e30f; }
                }
            }

            float rm0 = -1e30f, rm1 = -1e30f;
            #pragma unroll
            for (int nt = 0; nt < 8; nt++) {
                rm0 = fmaxf(rm0, fmaxf(sc[mtl][nt][0], sc[mtl][nt][1]));
                rm1 = fmaxf(rm1, fmaxf(sc[mtl][nt][2], sc[mtl][nt][3]));
            }
            rm0 = fmaxf(rm0, __shfl_xor_sync(0xffffffffu, rm0, 1));
            rm0 = fmaxf(rm0, __shfl_xor_sync(0xffffffffu, rm0, 2));
            rm1 = fmaxf(rm1, __shfl_xor_sync(0xffffffffu, rm1, 1));
            rm1 = fmaxf(rm1, __shfl_xor_sync(0xffffffffu, rm1, 2));

            float mn0 = fmaxf(m[mtl][0], rm0), mn1 = fmaxf(m[mtl][1], rm1);
            float al0 = __expf(m[mtl][0] - mn0), al1 = __expf(m[mtl][1] - mn1);
            float rs0 = 0.f, rs1 = 0.f;
            #pragma unroll
            for (int nt = 0; nt < 8; nt++) {
                float p0 = __expf(sc[mtl][nt][0] - mn0); sc[mtl][nt][0] = p0; rs0 += p0;
                float p1 = __expf(sc[mtl][nt][1] - mn0); sc[mtl][nt][1] = p1; rs0 += p1;
                float p2 = __expf(sc[mtl][nt][2] - mn1); sc[mtl][nt][2] = p2; rs1 += p2;
                float p3 = __expf(sc[mtl][nt][3] - mn1); sc[mtl][nt][3] = p3; rs1 += p3;
            }
            rs0 += __shfl_xor_sync(0xffffffffu, rs0, 1);
            rs0 += __shfl_xor_sync(0xffffffffu, rs0, 2);
            rs1 += __shfl_xor_sync(0xffffffffu, rs1, 1);
            rs1 += __shfl_xor_sync(0xffffffffu, rs1, 2);
            l[mtl][0] = l[mtl][0] * al0 + rs0; m[mtl][0] = mn0;
            l[mtl][1] = l[mtl][1] * al1 + rs1; m[mtl][1] = mn1;
            #pragma unroll
            for (int nt = 0; nt < 8; nt++) {
                acc[mtl][nt][0] *= al0; acc[mtl][nt][1] *= al0;
                acc[mtl][nt][2] *= al1; acc[mtl][nt][3] *= al1;
            }

            int pb = pw + mtl * 128 + g * 16;
            #pragma unroll
            for (int nt = 0; nt < 8; nt++) {
                int bb = pb + nt * 256;
                Pp[bb + t2a * 4 + s2a]     = f2tf(sc[mtl][nt][0]);
                Pp[bb + t2b * 4 + s2b]     = f2tf(sc[mtl][nt][1]);
                Pp[bb + t2a * 4 + s2a + 1] = f2tf(sc[mtl][nt][2]);
                Pp[bb + t2b * 4 + s2b + 1] = f2tf(sc[mtl][nt][3]);
            }
        }
        __syncwarp();

        // acc += P @ V
        #pragma unroll
        for (int ks = 0; ks < 8; ks++) {
            uint4 pa0 = *(uint4*)&Pp[pw + (ks * 2 + 0) * 128 + lane * 4];
            uint4 pa1 = *(uint4*)&Pp[pw + (ks * 2 + 1) * 128 + lane * 4];
            uint4 b0 = *(uint4*)&Vp[(ks * 4 + 0) * 128 + lane * 4];
            uint4 b1 = *(uint4*)&Vp[(ks * 4 + 1) * 128 + lane * 4];
            uint4 b2 = *(uint4*)&Vp[(ks * 4 + 2) * 128 + lane * 4];
            uint4 b3 = *(uint4*)&Vp[(ks * 4 + 3) * 128 + lane * 4];
            mma_tf32(acc[0][0], pa0.x, pa0.y, pa0.z, pa0.w, b0.x, b0.y);
            mma_tf32(acc[0][1], pa0.x, pa0.y, pa0.z, pa0.w, b0.z, b0.w);
            mma_tf32(acc[0][2], pa0.x, pa0.y, pa0.z, pa0.w, b1.x, b1.y);
            mma_tf32(acc[0][3], pa0.x, pa0.y, pa0.z, pa0.w, b1.z, b1.w);
            mma_tf32(acc[0][4], pa0.x, pa0.y, pa0.z, pa0.w, b2.x, b2.y);
            mma_tf32(acc[0][5], pa0.x, pa0.y, pa0.z, pa0.w, b2.z, b2.w);
            mma_tf32(acc[0][6], pa0.x, pa0.y, pa0.z, pa0.w, b3.x, b3.y);
            mma_tf32(acc[0][7], pa0.x, pa0.y, pa0.z, pa0.w, b3.z, b3.w);
            mma_tf32(acc[1][0], pa1.x, pa1.y, pa1.z, pa1.w, b0.x, b0.y);
            mma_tf32(acc[1][1], pa1.x, pa1.y, pa1.z, pa1.w, b0.z, b0.w);
            mma_tf32(acc[1][2], pa1.x, pa1.y, pa1.z, pa1.w, b1.x, b1.y);
            mma_tf32(acc[1][3], pa1.x, pa1.y, pa1.z, pa1.w, b1.z, b1.w);
            mma_tf32(acc[1][4], pa1.x, pa1.y, pa1.z, pa1.w, b2.x, b2.y);
            mma_tf32(acc[1][5], pa1.x, pa1.y, pa1.z, pa1.w, b2.z, b2.w);
            mma_tf32(acc[1][6], pa1.x, pa1.y, pa1.z, pa1.w, b3.x, b3.y);
            mma_tf32(acc[1][7], pa1.x, pa1.y, pa1.z, pa1.w, b3.z, b3.w);
        }
    }

    // epilogue
    #pragma unroll
    for (int mtl = 0; mtl < 2; mtl++) {
        float i0 = 1.0f / l[mtl][0], i1 = 1.0f / l[mtl][1];
        float* Og = g_ctx + ((size_t)h * SEQ + qb + warp * 32 + mtl * 16) * HD;
        #pragma unroll
        for (int nt = 0; nt < 8; nt++) {
            int col = nt * 8 + 2 * tg;
            *(float2*)&Og[(size_t)g * HD + col] =
                make_float2(acc[mtl][nt][0] * i0, acc[mtl][nt][1] * i0);
            *(float2*)&Og[(size_t)(g + 8) * HD + col] =
                make_float2(acc[mtl][nt][2] * i1, acc[mtl][nt][3] * i1);
        }
    }
}

// ---------------------------------------------------------------------------
extern "C" void kernel_launch(void* const* d_in, const int* in_sizes, int n_in,
                              void* d_out, int out_size) {
    const float* x  = (const float*)d_in[0];
    const float* Wq = (const float*)d_in[1];
    const float* bq = (const float*)d_in[2];
    const float* Wk = (const float*)d_in[3];
    const float* bk = (const float*)d_in[4];
    const float* Wv = (const float*)d_in[5];
    const float* bv = (const float*)d_in[6];
    const float* Wo = (const float*)d_in[7];
    const float* bo = (const float*)d_in[8];
    const int*   mask = (const int*)d_in[9];
    float* out = (float*)d_out;

    cudaFuncSetAttribute(flash_kernel, cudaFuncAttributeMaxDynamicSharedMemorySize,
                         FLASH_SMEM);

    compact_kernel<<<1, 1024>>>(mask);
    qkv_kernel<<<dim3(HDIM / 128, SEQ / 128, 3), 256>>>(x, Wq, bq, Wk, bk, Wv, bv);
    gather_permute_kernel<<<dim3(SEQ / 64, NHEAD), 128>>>();
    flash_kernel<<<dim3(SEQ / 128, NHEAD), 128, FLASH_SMEM>>>();
    oproj_kernel<<<dim3(HDIM / 128, SEQ / 128), 256>>>(Wo, bo, out);
}

// round 7
// speedup vs baseline: 6.8936x; 1.4287x over previous
#include <cuda_runtime.h>
#include <math.h>
#include <stdint.h>

#define SEQ  4096
#define HDIM 768
#define NHEAD 12
#define HD   64

#define NKT  (HDIM / 8)          // 96 k-tiles
#define XP_WORDS   (32 * NKT * 8 * 128)   // x / ctx permuted (M=4096)
#define WP_WORDS   (6  * NKT * 8 * 128)   // one weight matrix permuted (N=768)

// Scratch
__device__ float    g_q[NHEAD * SEQ * HD];
__device__ float    g_k[NHEAD * SEQ * HD];
__device__ float    g_v[NHEAD * SEQ * HD];
__device__ float    g_k2[NHEAD * SEQ * HD];  // K, fragment-permuted tf32
__device__ float    g_v2[NHEAD * SEQ * HD];  // V, fragment-permuted tf32
__device__ uint32_t g_xp[XP_WORDS];          // x, A-permuted tf32
__device__ uint32_t g_ctxp[XP_WORDS];        // ctx, A-permuted tf32
__device__ uint32_t g_wp[4][WP_WORDS];       // Wq,Wk,Wv,Wo B-permuted tf32
__device__ int      g_kidx[SEQ];
__device__ int      g_cnt;

__device__ __forceinline__ uint32_t f2tf(float f) {
    uint32_t u;
    asm("cvt.rna.tf32.f32 %0, %1;" : "=r"(u) : "f"(f));
    return u;
}

__device__ __forceinline__ void mma_tf32(float c[4],
                                         uint32_t a0, uint32_t a1, uint32_t a2, uint32_t a3,
                                         uint32_t b0, uint32_t b1) {
    asm volatile("mma.sync.aligned.m16n8k8.row.col.f32.tf32.tf32.f32 "
                 "{%0,%1,%2,%3}, {%4,%5,%6,%7}, {%8,%9}, {%0,%1,%2,%3};"
                 : "+f"(c[0]), "+f"(c[1]), "+f"(c[2]), "+f"(c[3])
                 : "r"(a0), "r"(a1), "r"(a2), "r"(a3), "r"(b0), "r"(b1));
}

__device__ __forceinline__ void cp16(uint32_t smem_addr, const void* gptr) {
    asm volatile("cp.async.cg.shared.global [%0], [%1], 16;"
                 :: "r"(smem_addr), "l"(gptr));
}
#define CP_COMMIT() asm volatile("cp.async.commit_group;")
#define CP_WAIT1()  asm volatile("cp.async.wait_group 1;")
#define CP_WAIT2()  asm volatile("cp.async.wait_group 2;")

// ---------------------------------------------------------------------------
// Compaction: stable scan of unmasked column indices (mask==0 keeps)
// ---------------------------------------------------------------------------
__global__ void compact_kernel(const int* __restrict__ mask) {
    __shared__ int wsum[32];
    int tid = threadIdx.x, lane = tid & 31, wid = tid >> 5;
    int f[4];
    int c = 0;
    #pragma unroll
    for (int r = 0; r < 4; r++) {
        f[r] = (mask[tid * 4 + r] == 0) ? 1 : 0;
        c += f[r];
    }
    int inc = c;
    #pragma unroll
    for (int o = 1; o < 32; o <<= 1) {
        int n = __shfl_up_sync(0xffffffffu, inc, o);
        if (lane >= o) inc += n;
    }
    if (lane == 31) wsum[wid] = inc;
    __syncthreads();
    if (wid == 0) {
        int v = wsum[lane];
        int s = v;
        #pragma unroll
        for (int o = 1; o < 32; o <<= 1) {
            int n = __shfl_up_sync(0xffffffffu, s, o);
            if (lane >= o) s += n;
        }
        wsum[lane] = s - v;
        if (lane == 31) g_cnt = s;
    }
    __syncthreads();
    int base = wsum[wid] + inc - c;
    #pragma unroll
    for (int r = 0; r < 4; r++) {
        if (f[r]) g_kidx[base++] = tid * 4 + r;
    }
}

// ---------------------------------------------------------------------------
// Permute x -> g_xp  (A-operand fragment layout, tf32)
// A subtile word(l,s): m = (s&1)*8 + (l>>2), k = (s>>1)*4 + (l&3)
// grid (96, 32), block 256: subtile st = tid>>5 (= m16 tile), lane = tid&31
// ---------------------------------------------------------------------------
__global__ __launch_bounds__(256)
void permute_x_kernel(const float* __restrict__ x) {
    int kt = blockIdx.x, mb = blockIdx.y;
    int st = threadIdx.x >> 5, l = threadIdx.x & 31;
    uint32_t w[4];
    #pragma unroll
    for (int s = 0; s < 4; s++) {
        int m = mb * 128 + st * 16 + (s & 1) * 8 + (l >> 2);
        int k = kt * 8 + (s >> 1) * 4 + (l & 3);
        w[s] = f2tf(x[(size_t)m * HDIM + k]);
    }
    *(uint4*)&g_xp[(((size_t)mb * NKT + kt) * 8 + st) * 128 + l * 4] = *(uint4*)w;
}

// ---------------------------------------------------------------------------
// Permute W -> g_wp[z] (B-operand fragment layout, tf32)
// B subtile word(l,s): n = (s>>1)*8 + (l>>2), k = (s&1)*4 + (l&3)
// grid (96, 6, 4), block 256
// ---------------------------------------------------------------------------
__global__ __launch_bounds__(256)
void permute_w_kernel(const float* __restrict__ Wq, const float* __restrict__ Wk,
                      const float* __restrict__ Wv, const float* __restrict__ Wo) {
    int kt = blockIdx.x, nb = blockIdx.y, z = blockIdx.z;
    const float* W = (z == 0) ? Wq : (z == 1) ? Wk : (z == 2) ? Wv : Wo;
    int st = threadIdx.x >> 5, l = threadIdx.x & 31;
    uint32_t w[4];
    #pragma unroll
    for (int s = 0; s < 4; s++) {
        int n = nb * 128 + st * 16 + (s >> 1) * 8 + (l >> 2);
        int k = kt * 8 + (s & 1) * 4 + (l & 3);
        w[s] = f2tf(W[(size_t)n * HDIM + k]);
    }
    *(uint4*)&g_wp[z][(((size_t)nb * NKT + kt) * 8 + st) * 128 + l * 4] = *(uint4*)w;
}

// ---------------------------------------------------------------------------
// Gather + fragment-permute + tf32 convert K/V into g_k2/g_v2 (unchanged).
// ---------------------------------------------------------------------------
__global__ __launch_bounds__(128)
void gather_permute_kernel() {
    int h = blockIdx.y;
    int T = blockIdx.x;
    int cnt = g_cnt;
    if (T * 64 >= cnt) return;
    int tid = threadIdx.x;
    int lane = tid & 31, warp = tid >> 5;
    const float* Kh = g_k + (size_t)h * SEQ * HD;
    const float* Vh = g_v + (size_t)h * SEQ * HD;
    uint32_t* dstK = (uint32_t*)g_k2 + ((size_t)h * 64 + T) * 4096;
    uint32_t* dstV = (uint32_t*)g_v2 + ((size_t)h * 64 + T) * 4096;
    int jb = T * 64;
    #pragma unroll
    for (int i = 0; i < 8; i++) {
        int st = warp * 8 + i;
        int hi = st >> 2, np = st & 3;
        {   // K
            uint32_t w[4];
            #pragma unroll
            for (int s = 0; s < 4; s++) {
                int d = hi * 8 + (s & 1) * 4 + (lane & 3);
                int j = jb + np * 16 + (s >> 1) * 8 + (lane >> 2);
                float v = (j < cnt) ? Kh[(size_t)g_kidx[j] * HD + d] : 0.0f;
                w[s] = f2tf(v);
            }
            *(uint4*)&dstK[st * 128 + lane * 4] = *(uint4*)w;
        }
        {   // V
            uint32_t w[4];
            #pragma unroll
            for (int s = 0; s < 4; s++) {
                int j = jb + hi * 8 + (s & 1) * 4 + (lane & 3);
                int d = np * 16 + (s >> 1) * 8 + (lane >> 2);
                float v = (j < cnt) ? Vh[(size_t)g_kidx[j] * HD + d] : 0.0f;
                w[s] = f2tf(v);
            }
            *(uint4*)&dstV[st * 128 + lane * 4] = *(uint4*)w;
        }
    }
}

// ---------------------------------------------------------------------------
// tf32 mma GEMM v2: operands pre-permuted in gmem, streamed via cp.async.
// CTA 128x128, BK=32, 3-stage pipeline, 256 thr = 8 warps (4m x 2n),
// warp tile 32x64. Stage = A 16KB + B 16KB. Dyn smem 96KB.
// ---------------------------------------------------------------------------
template<bool OHEAD>
__device__ __forceinline__ void gemm2_body(const uint32_t* __restrict__ Ap,
                                           const uint32_t* __restrict__ Bp,
                                           const float* __restrict__ bias,
                                           float* __restrict__ dst) {
    extern __shared__ uint32_t sg[];
    int tid = threadIdx.x;
    int lane = tid & 31, warp = tid >> 5;
    int g = lane >> 2, tg = lane & 3;
    int warp_m = warp & 3, warp_n = warp >> 2;
    int nb = blockIdx.x, mb = blockIdx.y;
    uint32_t smem_base = (uint32_t)__cvta_generic_to_shared(sg);

    const uint4* Asrc = (const uint4*)Ap + (size_t)mb * NKT * 256;
    const uint4* Bsrc = (const uint4*)Bp + (size_t)nb * NKT * 256;

    auto pf = [&](int s, int st) {
        uint32_t da = smem_base + (uint32_t)st * 8192u * 4u;
        const uint4* a = Asrc + (size_t)s * 1024;
        const uint4* b = Bsrc + (size_t)s * 1024;
        #pragma unroll
        for (int i = 0; i < 4; i++) {
            int o = i * 256 + tid;
            cp16(da + (uint32_t)o * 16u, a + o);
            cp16(da + 16384u + (uint32_t)o * 16u, b + o);
        }
    };

    pf(0, 0); CP_COMMIT();
    pf(1, 1); CP_COMMIT();
    pf(2, 2); CP_COMMIT();

    float acc[2][8][4] = {};
    const int NST = HDIM / 32;   // 24 stages

    for (int s = 0; s < NST; s++) {
        CP_WAIT2();
        __syncthreads();
        uint32_t* A = sg + (s % 3) * 8192;
        uint32_t* B = A + 4096;
        #pragma unroll
        for (int ktl = 0; ktl < 4; ktl++) {
            uint4 a0 = *(uint4*)&A[ktl * 1024 + (warp_m * 2 + 0) * 128 + lane * 4];
            uint4 a1 = *(uint4*)&A[ktl * 1024 + (warp_m * 2 + 1) * 128 + lane * 4];
            uint4 b0 = *(uint4*)&B[ktl * 1024 + (warp_n * 4 + 0) * 128 + lane * 4];
            uint4 b1 = *(uint4*)&B[ktl * 1024 + (warp_n * 4 + 1) * 128 + lane * 4];
            uint4 b2 = *(uint4*)&B[ktl * 1024 + (warp_n * 4 + 2) * 128 + lane * 4];
            uint4 b3 = *(uint4*)&B[ktl * 1024 + (warp_n * 4 + 3) * 128 + lane * 4];
            mma_tf32(acc[0][0], a0.x, a0.y, a0.z, a0.w, b0.x, b0.y);
            mma_tf32(acc[0][1], a0.x, a0.y, a0.z, a0.w, b0.z, b0.w);
            mma_tf32(acc[0][2], a0.x, a0.y, a0.z, a0.w, b1.x, b1.y);
            mma_tf32(acc[0][3], a0.x, a0.y, a0.z, a0.w, b1.z, b1.w);
            mma_tf32(acc[0][4], a0.x, a0.y, a0.z, a0.w, b2.x, b2.y);
            mma_tf32(acc[0][5], a0.x, a0.y, a0.z, a0.w, b2.z, b2.w);
            mma_tf32(acc[0][6], a0.x, a0.y, a0.z, a0.w, b3.x, b3.y);
            mma_tf32(acc[0][7], a0.x, a0.y, a0.z, a0.w, b3.z, b3.w);
            mma_tf32(acc[1][0], a1.x, a1.y, a1.z, a1.w, b0.x, b0.y);
            mma_tf32(acc[1][1], a1.x, a1.y, a1.z, a1.w, b0.z, b0.w);
            mma_tf32(acc[1][2], a1.x, a1.y, a1.z, a1.w, b1.x, b1.y);
            mma_tf32(acc[1][3], a1.x, a1.y, a1.z, a1.w, b1.z, b1.w);
            mma_tf32(acc[1][4], a1.x, a1.y, a1.z, a1.w, b2.x, b2.y);
            mma_tf32(acc[1][5], a1.x, a1.y, a1.z, a1.w, b2.z, b2.w);
            mma_tf32(acc[1][6], a1.x, a1.y, a1.z, a1.w, b3.x, b3.y);
            mma_tf32(acc[1][7], a1.x, a1.y, a1.z, a1.w, b3.z, b3.w);
        }
        __syncthreads();
        if (s + 3 < NST) pf(s + 3, s % 3);
        CP_COMMIT();
    }

    int mbase = mb * 128, nbase = nb * 128;
    #pragma unroll
    for (int i = 0; i < 2; i++) {
        int m0 = mbase + warp_m * 32 + i * 16 + g;
        #pragma unroll
        for (int nt = 0; nt < 8; nt++) {
            int n0 = nbase + warp_n * 64 + nt * 8 + 2 * tg;
            float bx = bias[n0], by = bias[n0 + 1];
            float2 v0 = make_float2(acc[i][nt][0] + bx, acc[i][nt][1] + by);
            float2 v1 = make_float2(acc[i][nt][2] + bx, acc[i][nt][3] + by);
            if (OHEAD) {
                float* p = dst + (((size_t)(n0 >> 6)) * SEQ + m0) * HD + (n0 & 63);
                *(float2*)p = v0;
                *(float2*)(p + 8 * HD) = v1;
            } else {
                *(float2*)(dst + (size_t)m0 * HDIM + n0) = v0;
                *(float2*)(dst + (size_t)(m0 + 8) * HDIM + n0) = v1;
            }
        }
    }
}

#define GEMM_SMEM (3 * 8192 * 4)

__global__ __launch_bounds__(256)
void qkv_kernel(const float* __restrict__ bq, const float* __restrict__ bk,
                const float* __restrict__ bv) {
    int z = blockIdx.z;
    const float* bias = (z == 0) ? bq : (z == 1) ? bk : bv;
    float* dst = (z == 0) ? g_q : (z == 1) ? g_k : g_v;
    gemm2_body<true>(g_xp, g_wp[z], bias, dst);
}

__global__ __launch_bounds__(256)
void oproj_kernel(const float* __restrict__ bo, float* __restrict__ out) {
    gemm2_body<false>(g_ctxp, g_wp[3], bo, out);
}

// ---------------------------------------------------------------------------
// Flash attention (R6 mainloop). Epilogue writes g_ctxp in A-permuted tf32.
// ---------------------------------------------------------------------------
#define FLASH_SMEM (24576 * 4)

__global__ __launch_bounds__(128)
void flash_kernel() {
    extern __shared__ uint32_t sm[];
    uint32_t* Pp = sm + 16384;

    int tid = threadIdx.x;
    int lane = tid & 31, warp = tid >> 5;
    int g = lane >> 2, tg = lane & 3;
    int h = blockIdx.y, qb = blockIdx.x * 128;
    int cnt = g_cnt;
    uint32_t smem_base = (uint32_t)__cvta_generic_to_shared(sm);

    // ---- Q staging (into Pp region) -> register fragments ----
    const float* Qg = g_q + ((size_t)h * SEQ + qb) * HD;
    #pragma unroll
    for (int r = 0; r < 16; r++) {
        int idx = r * 128 + tid;
        int row = idx >> 4, c4 = idx & 15;
        float4 v = *(const float4*)(Qg + (size_t)row * HD + c4 * 4);
        int base = ((c4 >> 1) * 8 + (row >> 4)) * 128 + (row & 7) * 16
                 + ((row >> 3) & 1) + 2 * (c4 & 1);
        Pp[base]      = f2tf(v.x);
        Pp[base + 4]  = f2tf(v.y);
        Pp[base + 8]  = f2tf(v.z);
        Pp[base + 12] = f2tf(v.w);
    }
    __syncthreads();
    uint4 q[8][2];
    #pragma unroll
    for (int ks = 0; ks < 8; ks++)
        #pragma unroll
        for (int mtl = 0; mtl < 2; mtl++)
            q[ks][mtl] = *(uint4*)&Pp[(ks * 8 + warp * 2 + mtl) * 128 + lane * 4];

    float m[2][2] = {{-1e30f, -1e30f}, {-1e30f, -1e30f}};
    float l[2][2] = {{0.f, 0.f}, {0.f, 0.f}};
    float acc[2][8][4] = {};

    const uint4* Ksrc = (const uint4*)((const uint32_t*)g_k2 + (size_t)h * 64 * 4096);
    const uint4* Vsrc = (const uint4*)((const uint32_t*)g_v2 + (size_t)h * 64 * 4096);
    int ntile = (cnt + 63) >> 6;

    int t2a = (2 * tg) & 3,     s2a = ((2 * tg) >> 2) * 2;
    int t2b = (2 * tg + 1) & 3, s2b = ((2 * tg + 1) >> 2) * 2;
    int pw = warp * 2048;

    auto prefetch = [&](int t, int buf) {
        uint32_t dk = smem_base + (uint32_t)(buf * 8192) * 4u;
        uint32_t dv = dk + 4096u * 4u;
        const uint4* sk = Ksrc + (size_t)t * 1024;
        const uint4* sv = Vsrc + (size_t)t * 1024;
        #pragma unroll
        for (int i = 0; i < 8; i++) {
            int o = i * 128 + tid;
            cp16(dk + (uint32_t)o * 16u, sk + o);
            cp16(dv + (uint32_t)o * 16u, sv + o);
        }
    };

    prefetch(0, 0);
    CP_COMMIT();

    for (int t = 0; t < ntile; t++) {
        int cur = t & 1;
        int kvb = t * 64;
        __syncthreads();
        if (t + 1 < ntile) prefetch(t + 1, cur ^ 1);
        CP_COMMIT();
        CP_WAIT1();
        __syncthreads();
        uint32_t* Kp = sm + cur * 8192;
        uint32_t* Vp = Kp + 4096;

        // S = Q K^T  (warp: 32x64)
        float sc[2][8][4] = {};
        #pragma unroll
        for (int ks = 0; ks < 8; ks++) {
            uint4 b0 = *(uint4*)&Kp[(ks * 4 + 0) * 128 + lane * 4];
            uint4 b1 = *(uint4*)&Kp[(ks * 4 + 1) * 128 + lane * 4];
            uint4 b2 = *(uint4*)&Kp[(ks * 4 + 2) * 128 + lane * 4];
            uint4 b3 = *(uint4*)&Kp[(ks * 4 + 3) * 128 + lane * 4];
            #pragma unroll
            for (int mtl = 0; mtl < 2; mtl++) {
                uint4 a = q[ks][mtl];
                mma_tf32(sc[mtl][0], a.x, a.y, a.z, a.w, b0.x, b0.y);
                mma_tf32(sc[mtl][1], a.x, a.y, a.z, a.w, b0.z, b0.w);
                mma_tf32(sc[mtl][2], a.x, a.y, a.z, a.w, b1.x, b1.y);
                mma_tf32(sc[mtl][3], a.x, a.y, a.z, a.w, b1.z, b1.w);
                mma_tf32(sc[mtl][4], a.x, a.y, a.z, a.w, b2.x, b2.y);
                mma_tf32(sc[mtl][5], a.x, a.y, a.z, a.w, b2.z, b2.w);
                mma_tf32(sc[mtl][6], a.x, a.y, a.z, a.w, b3.x, b3.y);
                mma_tf32(sc[mtl][7], a.x, a.y, a.z, a.w, b3.z, b3.w);
            }
        }

        bool tail = (kvb + 64 > cnt);

        #pragma unroll
        for (int mtl = 0; mtl < 2; mtl++) {
            #pragma unroll
            for (int nt = 0; nt < 8; nt++) {
                #pragma unroll
                for (int e = 0; e < 4; e++)
                    sc[mtl][nt][e] *= 0.125f;
            }
            if (tail) {
                #pragma unroll
                for (int nt = 0; nt < 8; nt++) {
                    int c0 = kvb + nt * 8 + 2 * tg;
                    if (c0     >= cnt) { sc[mtl][nt][0] = -1e30f; sc[mtl][nt][2] = -1e30f; }
                    if (c0 + 1 >= cnt) { sc[mtl][nt][1] = -1e30f; sc[mtl][nt][3] = -1e30f; }
                }
            }

            float rm0 = -1e30f, rm1 = -1e30f;
            #pragma unroll
            for (int nt = 0; nt < 8; nt++) {
                rm0 = fmaxf(rm0, fmaxf(sc[mtl][nt][0], sc[mtl][nt][1]));
                rm1 = fmaxf(rm1, fmaxf(sc[mtl][nt][2], sc[mtl][nt][3]));
            }
            rm0 = fmaxf(rm0, __shfl_xor_sync(0xffffffffu, rm0, 1));
            rm0 = fmaxf(rm0, __shfl_xor_sync(0xffffffffu, rm0, 2));
            rm1 = fmaxf(rm1, __shfl_xor_sync(0xffffffffu, rm1, 1));
            rm1 = fmaxf(rm1, __shfl_xor_sync(0xffffffffu, rm1, 2));

            float mn0 = fmaxf(m[mtl][0], rm0), mn1 = fmaxf(m[mtl][1], rm1);
            float al0 = __expf(m[mtl][0] - mn0), al1 = __expf(m[mtl][1] - mn1);
            float rs0 = 0.f, rs1 = 0.f;
            #pragma unroll
            for (int nt = 0; nt < 8; nt++) {
                float p0 = __expf(sc[mtl][nt][0] - mn0); sc[mtl][nt][0] = p0; rs0 += p0;
                float p1 = __expf(sc[mtl][nt][1] - mn0); sc[mtl][nt][1] = p1; rs0 += p1;
                float p2 = __expf(sc[mtl][nt][2] - mn1); sc[mtl][nt][2] = p2; rs1 += p2;
                float p3 = __expf(sc[mtl][nt][3] - mn1); sc[mtl][nt][3] = p3; rs1 += p3;
            }
            rs0 += __shfl_xor_sync(0xffffffffu, rs0, 1);
            rs0 += __shfl_xor_sync(0xffffffffu, rs0, 2);
            rs1 += __shfl_xor_sync(0xffffffffu, rs1, 1);
            rs1 += __shfl_xor_sync(0xffffffffu, rs1, 2);
            l[mtl][0] = l[mtl][0] * al0 + rs0; m[mtl][0] = mn0;
            l[mtl][1] = l[mtl][1] * al1 + rs1; m[mtl][1] = mn1;
            #pragma unroll
            for (int nt = 0; nt < 8; nt++) {
                acc[mtl][nt][0] *= al0; acc[mtl][nt][1] *= al0;
                acc[mtl][nt][2] *= al1; acc[mtl][nt][3] *= al1;
            }

            int pb = pw + mtl * 128 + g * 16;
            #pragma unroll
            for (int nt = 0; nt < 8; nt++) {
                int bb = pb + nt * 256;
                Pp[bb + t2a * 4 + s2a]     = f2tf(sc[mtl][nt][0]);
                Pp[bb + t2b * 4 + s2b]     = f2tf(sc[mtl][nt][1]);
                Pp[bb + t2a * 4 + s2a + 1] = f2tf(sc[mtl][nt][2]);
                Pp[bb + t2b * 4 + s2b + 1] = f2tf(sc[mtl][nt][3]);
            }
        }
        __syncwarp();

        // acc += P @ V
        #pragma unroll
        for (int ks = 0; ks < 8; ks++) {
            uint4 pa0 = *(uint4*)&Pp[pw + (ks * 2 + 0) * 128 + lane * 4];
            uint4 pa1 = *(uint4*)&Pp[pw + (ks * 2 + 1) * 128 + lane * 4];
            uint4 b0 = *(uint4*)&Vp[(ks * 4 + 0) * 128 + lane * 4];
            uint4 b1 = *(uint4*)&Vp[(ks * 4 + 1) * 128 + lane * 4];
            uint4 b2 = *(uint4*)&Vp[(ks * 4 + 2) * 128 + lane * 4];
            uint4 b3 = *(uint4*)&Vp[(ks * 4 + 3) * 128 + lane * 4];
            mma_tf32(acc[0][0], pa0.x, pa0.y, pa0.z, pa0.w, b0.x, b0.y);
            mma_tf32(acc[0][1], pa0.x, pa0.y, pa0.z, pa0.w, b0.z, b0.w);
            mma_tf32(acc[0][2], pa0.x, pa0.y, pa0.z, pa0.w, b1.x, b1.y);
            mma_tf32(acc[0][3], pa0.x, pa0.y, pa0.z, pa0.w, b1.z, b1.w);
            mma_tf32(acc[0][4], pa0.x, pa0.y, pa0.z, pa0.w, b2.x, b2.y);
            mma_tf32(acc[0][5], pa0.x, pa0.y, pa0.z, pa0.w, b2.z, b2.w);
            mma_tf32(acc[0][6], pa0.x, pa0.y, pa0.z, pa0.w, b3.x, b3.y);
            mma_tf32(acc[0][7], pa0.x, pa0.y, pa0.z, pa0.w, b3.z, b3.w);
            mma_tf32(acc[1][0], pa1.x, pa1.y, pa1.z, pa1.w, b0.x, b0.y);
            mma_tf32(acc[1][1], pa1.x, pa1.y, pa1.z, pa1.w, b0.z, b0.w);
            mma_tf32(acc[1][2], pa1.x, pa1.y, pa1.z, pa1.w, b1.x, b1.y);
            mma_tf32(acc[1][3], pa1.x, pa1.y, pa1.z, pa1.w, b1.z, b1.w);
            mma_tf32(acc[1][4], pa1.x, pa1.y, pa1.z, pa1.w, b2.x, b2.y);
            mma_tf32(acc[1][5], pa1.x, pa1.y, pa1.z, pa1.w, b2.z, b2.w);
            mma_tf32(acc[1][6], pa1.x, pa1.y, pa1.z, pa1.w, b3.x, b3.y);
            mma_tf32(acc[1][7], pa1.x, pa1.y, pa1.z, pa1.w, b3.z, b3.w);
        }
    }

    // epilogue: write ctx directly in A-permuted tf32 layout (for oproj cp.async)
    int mb = blockIdx.x;
    #pragma unroll
    for (int mtl = 0; mtl < 2; mtl++) {
        float i0 = 1.0f / l[mtl][0], i1 = 1.0f / l[mtl][1];
        int mt = warp * 2 + mtl;
        #pragma unroll
        for (int nt = 0; nt < 8; nt++) {
            uint32_t base = (((uint32_t)mb * NKT + (h * 8 + nt)) * 8 + mt) * 128 + g * 16;
            g_ctxp[base + t2a * 4 + s2a]     = f2tf(acc[mtl][nt][0] * i0);
            g_ctxp[base + t2b * 4 + s2b]     = f2tf(acc[mtl][nt][1] * i0);
            g_ctxp[base + t2a * 4 + s2a + 1] = f2tf(acc[mtl][nt][2] * i1);
            g_ctxp[base + t2b * 4 + s2b + 1] = f2tf(acc[mtl][nt][3] * i1);
        }
    }
}

// ---------------------------------------------------------------------------
extern "C" void kernel_launch(void* const* d_in, const int* in_sizes, int n_in,
                              void* d_out, int out_size) {
    const float* x  = (const float*)d_in[0];
    const float* Wq = (const float*)d_in[1];
    const float* bq = (const float*)d_in[2];
    const float* Wk = (const float*)d_in[3];
    const float* bk = (const float*)d_in[4];
    const float* Wv = (const float*)d_in[5];
    const float* bv = (const float*)d_in[6];
    const float* Wo = (const float*)d_in[7];
    const float* bo = (const float*)d_in[8];
    const int*   mask = (const int*)d_in[9];
    float* out = (float*)d_out;

    cudaFuncSetAttribute(flash_kernel, cudaFuncAttributeMaxDynamicSharedMemorySize,
                         FLASH_SMEM);
    cudaFuncSetAttribute(qkv_kernel, cudaFuncAttributeMaxDynamicSharedMemorySize,
                         GEMM_SMEM);
    cudaFuncSetAttribute(oproj_kernel, cudaFuncAttributeMaxDynamicSharedMemorySize,
                         GEMM_SMEM);

    compact_kernel<<<1, 1024>>>(mask);
    permute_x_kernel<<<dim3(NKT, 32), 256>>>(x);
    permute_w_kernel<<<dim3(NKT, 6, 4), 256>>>(Wq, Wk, Wv, Wo);
    qkv_kernel<<<dim3(6, 32, 3), 256, GEMM_SMEM>>>(bq, bk, bv);
    gather_permute_kernel<<<dim3(SEQ / 64, NHEAD), 128>>>();
    flash_kernel<<<dim3(SEQ / 128, NHEAD), 128, FLASH_SMEM>>>();
    oproj_kernel<<<dim3(6, 32), 256, GEMM_SMEM>>>(bo, out);
}

// round 8
// speedup vs baseline: 7.4088x; 1.0747x over previous
#include <cuda_runtime.h>
#include <math.h>
#include <stdint.h>

#define SEQ  4096
#define HDIM 768
#define NHEAD 12
#define HD   64

#define NKT  (HDIM / 8)                   // 96 k-tiles
#define XP_WORDS   (32 * NKT * 8 * 128)   // A-permuted M=4096 operand
#define WP_WORDS   (6  * NKT * 8 * 128)   // B-permuted N=768 operand

// Scratch
__device__ uint32_t g_qp[XP_WORDS / 4 * 4];   // Q, flash-A-fragment tf32 (12.6MB)
__device__ float    g_k2[NHEAD * SEQ * HD];   // K, flash-B-fragment tf32
__device__ float    g_v2[NHEAD * SEQ * HD];   // V, flash-B-fragment tf32
__device__ uint32_t g_xp[XP_WORDS];           // x, A-permuted tf32
__device__ uint32_t g_xkvp[XP_WORDS];         // x gathered by kidx, A-permuted tf32
__device__ uint32_t g_ctxp[XP_WORDS];         // ctx, A-permuted tf32
__device__ uint32_t g_wp[4][WP_WORDS];        // Wq,Wk,Wv,Wo B-permuted tf32
__device__ int      g_kidx[SEQ];
__device__ int      g_cnt;

__device__ __forceinline__ uint32_t f2tf(float f) {
    uint32_t u;
    asm("cvt.rna.tf32.f32 %0, %1;" : "=r"(u) : "f"(f));
    return u;
}

__device__ __forceinline__ void mma_tf32(float c[4],
                                         uint32_t a0, uint32_t a1, uint32_t a2, uint32_t a3,
                                         uint32_t b0, uint32_t b1) {
    asm volatile("mma.sync.aligned.m16n8k8.row.col.f32.tf32.tf32.f32 "
                 "{%0,%1,%2,%3}, {%4,%5,%6,%7}, {%8,%9}, {%0,%1,%2,%3};"
                 : "+f"(c[0]), "+f"(c[1]), "+f"(c[2]), "+f"(c[3])
                 : "r"(a0), "r"(a1), "r"(a2), "r"(a3), "r"(b0), "r"(b1));
}

__device__ __forceinline__ void cp16(uint32_t smem_addr, const void* gptr) {
    asm volatile("cp.async.cg.shared.global [%0], [%1], 16;"
                 :: "r"(smem_addr), "l"(gptr));
}
#define CP_COMMIT() asm volatile("cp.async.commit_group;")
#define CP_WAIT1()  asm volatile("cp.async.wait_group 1;")
#define CP_WAIT2()  asm volatile("cp.async.wait_group 2;")

// ---------------------------------------------------------------------------
// Compaction: stable scan of unmasked column indices (mask==0 keeps)
// ---------------------------------------------------------------------------
__global__ void compact_kernel(const int* __restrict__ mask) {
    __shared__ int wsum[32];
    int tid = threadIdx.x, lane = tid & 31, wid = tid >> 5;
    int f[4];
    int c = 0;
    #pragma unroll
    for (int r = 0; r < 4; r++) {
        f[r] = (mask[tid * 4 + r] == 0) ? 1 : 0;
        c += f[r];
    }
    int inc = c;
    #pragma unroll
    for (int o = 1; o < 32; o <<= 1) {
        int n = __shfl_up_sync(0xffffffffu, inc, o);
        if (lane >= o) inc += n;
    }
    if (lane == 31) wsum[wid] = inc;
    __syncthreads();
    if (wid == 0) {
        int v = wsum[lane];
        int s = v;
        #pragma unroll
        for (int o = 1; o < 32; o <<= 1) {
            int n = __shfl_up_sync(0xffffffffu, s, o);
            if (lane >= o) s += n;
        }
        wsum[lane] = s - v;
        if (lane == 31) g_cnt = s;
    }
    __syncthreads();
    int base = wsum[wid] + inc - c;
    #pragma unroll
    for (int r = 0; r < 4; r++) {
        if (f[r]) g_kidx[base++] = tid * 4 + r;
    }
}

// ---------------------------------------------------------------------------
// Permute x -> g_xp (A-fragment layout, tf32). grid (96, 32), block 256.
// A subtile word(l,s): m = (s&1)*8 + (l>>2), k = (s>>1)*4 + (l&3)
// ---------------------------------------------------------------------------
__global__ __launch_bounds__(256)
void permute_x_kernel(const float* __restrict__ x) {
    int kt = blockIdx.x, mb = blockIdx.y;
    int st = threadIdx.x >> 5, l = threadIdx.x & 31;
    uint32_t w[4];
    #pragma unroll
    for (int s = 0; s < 4; s++) {
        int m = mb * 128 + st * 16 + (s & 1) * 8 + (l >> 2);
        int k = kt * 8 + (s >> 1) * 4 + (l & 3);
        w[s] = f2tf(x[(size_t)m * HDIM + k]);
    }
    *(uint4*)&g_xp[(((size_t)mb * NKT + kt) * 8 + st) * 128 + l * 4] = *(uint4*)w;
}

// ---------------------------------------------------------------------------
// Permute gathered x rows (kidx) -> g_xkvp, zero-padded past cnt.
// ---------------------------------------------------------------------------
__global__ __launch_bounds__(256)
void permute_xkv_kernel(const float* __restrict__ x) {
    int kt = blockIdx.x, mb = blockIdx.y;
    int cnt = g_cnt;
    if (mb * 128 >= cnt) return;
    int st = threadIdx.x >> 5, l = threadIdx.x & 31;
    uint32_t w[4];
    #pragma unroll
    for (int s = 0; s < 4; s++) {
        int m = mb * 128 + st * 16 + (s & 1) * 8 + (l >> 2);
        int k = kt * 8 + (s >> 1) * 4 + (l & 3);
        float v = (m < cnt) ? x[(size_t)g_kidx[m] * HDIM + k] : 0.0f;
        w[s] = f2tf(v);
    }
    *(uint4*)&g_xkvp[(((size_t)mb * NKT + kt) * 8 + st) * 128 + l * 4] = *(uint4*)w;
}

// ---------------------------------------------------------------------------
// Permute W -> g_wp[z] (B-fragment layout, tf32). grid (96, 6, 4), block 256.
// B subtile word(l,s): n = (s>>1)*8 + (l>>2), k = (s&1)*4 + (l&3)
// ---------------------------------------------------------------------------
__global__ __launch_bounds__(256)
void permute_w_kernel(const float* __restrict__ Wq, const float* __restrict__ Wk,
                      const float* __restrict__ Wv, const float* __restrict__ Wo) {
    int kt = blockIdx.x, nb = blockIdx.y, z = blockIdx.z;
    const float* W = (z == 0) ? Wq : (z == 1) ? Wk : (z == 2) ? Wv : Wo;
    int st = threadIdx.x >> 5, l = threadIdx.x & 31;
    uint32_t w[4];
    #pragma unroll
    for (int s = 0; s < 4; s++) {
        int n = nb * 128 + st * 16 + (s >> 1) * 8 + (l >> 2);
        int k = kt * 8 + (s & 1) * 4 + (l & 3);
        w[s] = f2tf(W[(size_t)n * HDIM + k]);
    }
    *(uint4*)&g_wp[z][(((size_t)nb * NKT + kt) * 8 + st) * 128 + l * 4] = *(uint4*)w;
}

// ---------------------------------------------------------------------------
// GEMM mainloop: operands pre-permuted in gmem, streamed via cp.async.
// CTA 128x128, BK=32, 3-stage pipeline, 256 thr = 8 warps (4m x 2n).
// ---------------------------------------------------------------------------
__device__ __forceinline__ void gemm_main(uint32_t* sg,
                                          const uint32_t* __restrict__ Ap,
                                          const uint32_t* __restrict__ Bp,
                                          float acc[2][8][4]) {
    int tid = threadIdx.x;
    int lane = tid & 31, warp = tid >> 5;
    int warp_m = warp & 3, warp_n = warp >> 2;
    uint32_t smem_base = (uint32_t)__cvta_generic_to_shared(sg);

    const uint4* Asrc = (const uint4*)Ap;
    const uint4* Bsrc = (const uint4*)Bp;

    auto pf = [&](int s, int st) {
        uint32_t da = smem_base + (uint32_t)st * 8192u * 4u;
        const uint4* a = Asrc + (size_t)s * 1024;
        const uint4* b = Bsrc + (size_t)s * 1024;
        #pragma unroll
        for (int i = 0; i < 4; i++) {
            int o = i * 256 + tid;
            cp16(da + (uint32_t)o * 16u, a + o);
            cp16(da + 16384u + (uint32_t)o * 16u, b + o);
        }
    };

    pf(0, 0); CP_COMMIT();
    pf(1, 1); CP_COMMIT();
    pf(2, 2); CP_COMMIT();

    const int NST = HDIM / 32;   // 24 stages
    for (int s = 0; s < NST; s++) {
        CP_WAIT2();
        __syncthreads();
        uint32_t* A = sg + (s % 3) * 8192;
        uint32_t* B = A + 4096;
        #pragma unroll
        for (int ktl = 0; ktl < 4; ktl++) {
            uint4 a0 = *(uint4*)&A[ktl * 1024 + (warp_m * 2 + 0) * 128 + lane * 4];
            uint4 a1 = *(uint4*)&A[ktl * 1024 + (warp_m * 2 + 1) * 128 + lane * 4];
            uint4 b0 = *(uint4*)&B[ktl * 1024 + (warp_n * 4 + 0) * 128 + lane * 4];
            uint4 b1 = *(uint4*)&B[ktl * 1024 + (warp_n * 4 + 1) * 128 + lane * 4];
            uint4 b2 = *(uint4*)&B[ktl * 1024 + (warp_n * 4 + 2) * 128 + lane * 4];
            uint4 b3 = *(uint4*)&B[ktl * 1024 + (warp_n * 4 + 3) * 128 + lane * 4];
            mma_tf32(acc[0][0], a0.x, a0.y, a0.z, a0.w, b0.x, b0.y);
            mma_tf32(acc[0][1], a0.x, a0.y, a0.z, a0.w, b0.z, b0.w);
            mma_tf32(acc[0][2], a0.x, a0.y, a0.z, a0.w, b1.x, b1.y);
            mma_tf32(acc[0][3], a0.x, a0.y, a0.z, a0.w, b1.z, b1.w);
            mma_tf32(acc[0][4], a0.x, a0.y, a0.z, a0.w, b2.x, b2.y);
            mma_tf32(acc[0][5], a0.x, a0.y, a0.z, a0.w, b2.z, b2.w);
            mma_tf32(acc[0][6], a0.x, a0.y, a0.z, a0.w, b3.x, b3.y);
            mma_tf32(acc[0][7], a0.x, a0.y, a0.z, a0.w, b3.z, b3.w);
            mma_tf32(acc[1][0], a1.x, a1.y, a1.z, a1.w, b0.x, b0.y);
            mma_tf32(acc[1][1], a1.x, a1.y, a1.z, a1.w, b0.z, b0.w);
            mma_tf32(acc[1][2], a1.x, a1.y, a1.z, a1.w, b1.x, b1.y);
            mma_tf32(acc[1][3], a1.x, a1.y, a1.z, a1.w, b1.z, b1.w);
            mma_tf32(acc[1][4], a1.x, a1.y, a1.z, a1.w, b2.x, b2.y);
            mma_tf32(acc[1][5], a1.x, a1.y, a1.z, a1.w, b2.z, b2.w);
            mma_tf32(acc[1][6], a1.x, a1.y, a1.z, a1.w, b3.x, b3.y);
            mma_tf32(acc[1][7], a1.x, a1.y, a1.z, a1.w, b3.z, b3.w);
        }
        __syncthreads();
        if (s + 3 < NST) pf(s + 3, s % 3);
        CP_COMMIT();
    }
}

#define GEMM_SMEM (3 * 8192 * 4)

// ---------------------------------------------------------------------------
// Fused projection kernel. z=0: Q over full x (M=4096) -> g_qp (A-fragment).
// z=1,2: K,V over gathered x (M=cnt) -> g_k2/g_v2 (flash B-fragment layouts).
// grid (6, 32, 3), block 256.
// ---------------------------------------------------------------------------
__global__ __launch_bounds__(256)
void proj_kernel(const float* __restrict__ bq, const float* __restrict__ bk,
                 const float* __restrict__ bv) {
    extern __shared__ uint32_t sg[];
    int z = blockIdx.z;
    int mb = blockIdx.y, nbh = blockIdx.x * 2;
    int cnt = g_cnt;
    if (z > 0 && mb * 128 >= cnt) return;

    const uint32_t* Ap = ((z == 0) ? g_xp : g_xkvp) + (size_t)mb * NKT * 1024;
    const uint32_t* Bp = g_wp[z] + (size_t)blockIdx.x * NKT * 1024;
    const float* bias = (z == 0) ? bq : (z == 1) ? bk : bv;

    float acc[2][8][4] = {};
    gemm_main(sg, Ap, Bp, acc);

    int tid = threadIdx.x;
    int lane = tid & 31, warp = tid >> 5;
    int g = lane >> 2, tg = lane & 3;
    int warp_m = warp & 3, warp_n = warp >> 2;
    int h = nbh + warp_n;

    if (z == 0) {
        // Q -> g_qp, A-fragment layout per (mb, h): subtile ks*8+mt
        uint32_t subbase = ((uint32_t)(mb * NHEAD + h) * 64) * 128;
        #pragma unroll
        for (int i = 0; i < 2; i++) {
            int mt = warp_m * 2 + i;
            #pragma unroll
            for (int nt = 0; nt < 8; nt++) {
                int d0 = nt * 8 + 2 * tg;
                float bx = bias[h * 64 + d0], by = bias[h * 64 + d0 + 1];
                int l0 = g * 4 + (d0 & 3);
                int bd = (d0 >> 2) & 1;
                uint32_t o = subbase + (uint32_t)(nt * 8 + mt) * 128 + l0 * 4 + 2 * bd;
                uint2 v0 = make_uint2(f2tf(acc[i][nt][0] + bx), f2tf(acc[i][nt][2] + bx));
                *(uint2*)&g_qp[o] = v0;
                uint2 v1 = make_uint2(f2tf(acc[i][nt][1] + by), f2tf(acc[i][nt][3] + by));
                *(uint2*)&g_qp[o + 4] = v1;
            }
        }
    } else if (z == 1) {
        // K -> g_k2: per (h, T): subtile (d-octet)*4 + np
        uint32_t* dst = (uint32_t*)g_k2;
        #pragma unroll
        for (int i = 0; i < 2; i++) {
            int j0 = mb * 128 + warp_m * 32 + i * 16 + g;
            #pragma unroll
            for (int nt = 0; nt < 8; nt++) {
                int d0 = nt * 8 + 2 * tg;
                float bx = bias[h * 64 + d0], by = bias[h * 64 + d0 + 1];
                #pragma unroll
                for (int r = 0; r < 2; r++) {
                    int j = j0 + r * 8;
                    int T = j >> 6;
                    int np = (j & 63) >> 4;
                    uint32_t base = (((uint32_t)h * 64 + T) * 32 + nt * 4 + np) * 128;
                    #pragma unroll
                    for (int c = 0; c < 2; c++) {
                        int dl = 2 * tg + c;
                        int l = g * 4 + (dl & 3);
                        int s = ((dl >> 2) & 1) + 2 * r;
                        dst[base + l * 4 + s] =
                            f2tf(acc[i][nt][r * 2 + c] + (c ? by : bx));
                    }
                }
            }
        }
    } else {
        // V -> g_v2: per (h, T): subtile (j-octet)*4 + (d>>4)
        uint32_t* dst = (uint32_t*)g_v2;
        #pragma unroll
        for (int i = 0; i < 2; i++) {
            int j0 = mb * 128 + warp_m * 32 + i * 16 + g;
            #pragma unroll
            for (int nt = 0; nt < 8; nt++) {
                int d0 = nt * 8 + 2 * tg;
                float bx = bias[h * 64 + d0], by = bias[h * 64 + d0 + 1];
                int sbit = ((g >> 2) & 1) + 2 * (nt & 1);
                #pragma unroll
                for (int r = 0; r < 2; r++) {
                    int j = j0 + r * 8;
                    int T = j >> 6;
                    int hi = (j & 63) >> 3;
                    uint32_t base = (((uint32_t)h * 64 + T) * 32 + hi * 4 + (nt >> 1)) * 128;
                    #pragma unroll
                    for (int c = 0; c < 2; c++) {
                        int d = d0 + c;
                        int l = (d & 7) * 4 + (j & 3);
                        dst[base + l * 4 + sbit] =
                            f2tf(acc[i][nt][r * 2 + c] + (c ? by : bx));
                    }
                }
            }
        }
    }
}

__global__ __launch_bounds__(256)
void oproj_kernel(const float* __restrict__ bo, float* __restrict__ out) {
    extern __shared__ uint32_t sg[];
    int mb = blockIdx.y;
    float acc[2][8][4] = {};
    gemm_main(sg, g_ctxp + (size_t)mb * NKT * 1024,
              g_wp[3] + (size_t)blockIdx.x * NKT * 1024, acc);

    int tid = threadIdx.x;
    int lane = tid & 31, warp = tid >> 5;
    int g = lane >> 2, tg = lane & 3;
    int warp_m = warp & 3, warp_n = warp >> 2;
    int mbase = mb * 128, nbase = blockIdx.x * 128;
    #pragma unroll
    for (int i = 0; i < 2; i++) {
        int m0 = mbase + warp_m * 32 + i * 16 + g;
        #pragma unroll
        for (int nt = 0; nt < 8; nt++) {
            int n0 = nbase + warp_n * 64 + nt * 8 + 2 * tg;
            float bx = bo[n0], by = bo[n0 + 1];
            *(float2*)(out + (size_t)m0 * HDIM + n0) =
                make_float2(acc[i][nt][0] + bx, acc[i][nt][1] + by);
            *(float2*)(out + (size_t)(m0 + 8) * HDIM + n0) =
                make_float2(acc[i][nt][2] + bx, acc[i][nt][3] + by);
        }
    }
}

// ---------------------------------------------------------------------------
// Flash attention. CTA = (head, 128 q rows), 128 thr = 4 warps x m32.
// Q fragments via LDG.128 from g_qp (pre-permuted). K/V streamed cp.async,
// double-buffered. Epilogue writes g_ctxp in A-fragment tf32.
// Smem: Kbuf0|Vbuf0 32KB, Kbuf1|Vbuf1 32KB, Pp 32KB.
// ---------------------------------------------------------------------------
#define FLASH_SMEM (24576 * 4)

__global__ __launch_bounds__(128)
void flash_kernel() {
    extern __shared__ uint32_t sm[];
    uint32_t* Pp = sm + 16384;

    int tid = threadIdx.x;
    int lane = tid & 31, warp = tid >> 5;
    int g = lane >> 2, tg = lane & 3;
    int h = blockIdx.y, mb = blockIdx.x;
    int cnt = g_cnt;
    uint32_t smem_base = (uint32_t)__cvta_generic_to_shared(sm);

    const uint4* Ksrc = (const uint4*)((const uint32_t*)g_k2 + (size_t)h * 64 * 4096);
    const uint4* Vsrc = (const uint4*)((const uint32_t*)g_v2 + (size_t)h * 64 * 4096);
    int ntile = (cnt + 63) >> 6;

    auto prefetch = [&](int t, int buf) {
        uint32_t dk = smem_base + (uint32_t)(buf * 8192) * 4u;
        uint32_t dv = dk + 4096u * 4u;
        const uint4* sk = Ksrc + (size_t)t * 1024;
        const uint4* sv = Vsrc + (size_t)t * 1024;
        #pragma unroll
        for (int i = 0; i < 8; i++) {
            int o = i * 128 + tid;
            cp16(dk + (uint32_t)o * 16u, sk + o);
            cp16(dv + (uint32_t)o * 16u, sv + o);
        }
    };

    prefetch(0, 0);
    CP_COMMIT();

    // Q fragments straight from pre-permuted gmem (overlaps with prefetch)
    const uint32_t* Qsrc = g_qp + ((size_t)(mb * NHEAD + h) * 64) * 128;
    uint4 q[8][2];
    #pragma unroll
    for (int ks = 0; ks < 8; ks++)
        #pragma unroll
        for (int mtl = 0; mtl < 2; mtl++)
            q[ks][mtl] = *(const uint4*)&Qsrc[(ks * 8 + warp * 2 + mtl) * 128 + lane * 4];

    float m[2][2] = {{-1e30f, -1e30f}, {-1e30f, -1e30f}};
    float l[2][2] = {{0.f, 0.f}, {0.f, 0.f}};
    float acc[2][8][4] = {};

    int t2a = (2 * tg) & 3,     s2a = ((2 * tg) >> 2) * 2;
    int t2b = (2 * tg + 1) & 3, s2b = ((2 * tg + 1) >> 2) * 2;
    int pw = warp * 2048;

    for (int t = 0; t < ntile; t++) {
        int cur = t & 1;
        int kvb = t * 64;
        __syncthreads();
        if (t + 1 < ntile) prefetch(t + 1, cur ^ 1);
        CP_COMMIT();
        CP_WAIT1();
        __syncthreads();
        uint32_t* Kp = sm + cur * 8192;
        uint32_t* Vp = Kp + 4096;

        // S = Q K^T  (warp: 32x64)
        float sc[2][8][4] = {};
        #pragma unroll
        for (int ks = 0; ks < 8; ks++) {
            uint4 b0 = *(uint4*)&Kp[(ks * 4 + 0) * 128 + lane * 4];
            uint4 b1 = *(uint4*)&Kp[(ks * 4 + 1) * 128 + lane * 4];
            uint4 b2 = *(uint4*)&Kp[(ks * 4 + 2) * 128 + lane * 4];
            uint4 b3 = *(uint4*)&Kp[(ks * 4 + 3) * 128 + lane * 4];
            #pragma unroll
            for (int mtl = 0; mtl < 2; mtl++) {
                uint4 a = q[ks][mtl];
                mma_tf32(sc[mtl][0], a.x, a.y, a.z, a.w, b0.x, b0.y);
                mma_tf32(sc[mtl][1], a.x, a.y, a.z, a.w, b0.z, b0.w);
                mma_tf32(sc[mtl][2], a.x, a.y, a.z, a.w, b1.x, b1.y);
                mma_tf32(sc[mtl][3], a.x, a.y, a.z, a.w, b1.z, b1.w);
                mma_tf32(sc[mtl][4], a.x, a.y, a.z, a.w, b2.x, b2.y);
                mma_tf32(sc[mtl][5], a.x, a.y, a.z, a.w, b2.z, b2.w);
                mma_tf32(sc[mtl][6], a.x, a.y, a.z, a.w, b3.x, b3.y);
                mma_tf32(sc[mtl][7], a.x, a.y, a.z, a.w, b3.z, b3.w);
            }
        }

        bool tail = (kvb + 64 > cnt);

        #pragma unroll
        for (int mtl = 0; mtl < 2; mtl++) {
            #pragma unroll
            for (int nt = 0; nt < 8; nt++) {
                #pragma unroll
                for (int e = 0; e < 4; e++)
                    sc[mtl][nt][e] *= 0.125f;
            }
            if (tail) {
                #pragma unroll
                for (int nt = 0; nt < 8; nt++) {
                    int c0 = kvb + nt * 8 + 2 * tg;
                    if (c0     >= cnt) { sc[mtl][nt][0] = -1e30f; sc[mtl][nt][2] = -1e30f; }
                    if (c0 + 1 >= cnt) { sc[mtl][nt][1] = -1e30f; sc[mtl][nt][3] = -1e30f; }
                }
            }

            float rm0 = -1e30f, rm1 = -1e30f;
            #pragma unroll
            for (int nt = 0; nt < 8; nt++) {
                rm0 = fmaxf(rm0, fmaxf(sc[mtl][nt][0], sc[mtl][nt][1]));
                rm1 = fmaxf(rm1, fmaxf(sc[mtl][nt][2], sc[mtl][nt][3]));
            }
            rm0 = fmaxf(rm0, __shfl_xor_sync(0xffffffffu, rm0, 1));
            rm0 = fmaxf(rm0, __shfl_xor_sync(0xffffffffu, rm0, 2));
            rm1 = fmaxf(rm1, __shfl_xor_sync(0xffffffffu, rm1, 1));
            rm1 = fmaxf(rm1, __shfl_xor_sync(0xffffffffu, rm1, 2));

            float mn0 = fmaxf(m[mtl][0], rm0), mn1 = fmaxf(m[mtl][1], rm1);
            float al0 = __expf(m[mtl][0] - mn0), al1 = __expf(m[mtl][1] - mn1);
            float rs0 = 0.f, rs1 = 0.f;
            #pragma unroll
            for (int nt = 0; nt < 8; nt++) {
                float p0 = __expf(sc[mtl][nt][0] - mn0); sc[mtl][nt][0] = p0; rs0 += p0;
                float p1 = __expf(sc[mtl][nt][1] - mn0); sc[mtl][nt][1] = p1; rs0 += p1;
                float p2 = __expf(sc[mtl][nt][2] - mn1); sc[mtl][nt][2] = p2; rs1 += p2;
                float p3 = __expf(sc[mtl][nt][3] - mn1); sc[mtl][nt][3] = p3; rs1 += p3;
            }
            rs0 += __shfl_xor_sync(0xffffffffu, rs0, 1);
            rs0 += __shfl_xor_sync(0xffffffffu, rs0, 2);
            rs1 += __shfl_xor_sync(0xffffffffu, rs1, 1);
            rs1 += __shfl_xor_sync(0xffffffffu, rs1, 2);
            l[mtl][0] = l[mtl][0] * al0 + rs0; m[mtl][0] = mn0;
            l[mtl][1] = l[mtl][1] * al1 + rs1; m[mtl][1] = mn1;
            #pragma unroll
            for (int nt = 0; nt < 8; nt++) {
                acc[mtl][nt][0] *= al0; acc[mtl][nt][1] *= al0;
                acc[mtl][nt][2] *= al1; acc[mtl][nt][3] *= al1;
            }

            int pb = pw + mtl * 128 + g * 16;
            #pragma unroll
            for (int nt = 0; nt < 8; nt++) {
                int bb = pb + nt * 256;
                Pp[bb + t2a * 4 + s2a]     = f2tf(sc[mtl][nt][0]);
                Pp[bb + t2b * 4 + s2b]     = f2tf(sc[mtl][nt][1]);
                Pp[bb + t2a * 4 + s2a + 1] = f2tf(sc[mtl][nt][2]);
                Pp[bb + t2b * 4 + s2b + 1] = f2tf(sc[mtl][nt][3]);
            }
        }
        __syncwarp();

        // acc += P @ V
        #pragma unroll
        for (int ks = 0; ks < 8; ks++) {
            uint4 pa0 = *(uint4*)&Pp[pw + (ks * 2 + 0) * 128 + lane * 4];
            uint4 pa1 = *(uint4*)&Pp[pw + (ks * 2 + 1) * 128 + lane * 4];
            uint4 b0 = *(uint4*)&Vp[(ks * 4 + 0) * 128 + lane * 4];
            uint4 b1 = *(uint4*)&Vp[(ks * 4 + 1) * 128 + lane * 4];
            uint4 b2 = *(uint4*)&Vp[(ks * 4 + 2) * 128 + lane * 4];
            uint4 b3 = *(uint4*)&Vp[(ks * 4 + 3) * 128 + lane * 4];
            mma_tf32(acc[0][0], pa0.x, pa0.y, pa0.z, pa0.w, b0.x, b0.y);
            mma_tf32(acc[0][1], pa0.x, pa0.y, pa0.z, pa0.w, b0.z, b0.w);
            mma_tf32(acc[0][2], pa0.x, pa0.y, pa0.z, pa0.w, b1.x, b1.y);
            mma_tf32(acc[0][3], pa0.x, pa0.y, pa0.z, pa0.w, b1.z, b1.w);
            mma_tf32(acc[0][4], pa0.x, pa0.y, pa0.z, pa0.w, b2.x, b2.y);
            mma_tf32(acc[0][5], pa0.x, pa0.y, pa0.z, pa0.w, b2.z, b2.w);
            mma_tf32(acc[0][6], pa0.x, pa0.y, pa0.z, pa0.w, b3.x, b3.y);
            mma_tf32(acc[0][7], pa0.x, pa0.y, pa0.z, pa0.w, b3.z, b3.w);
            mma_tf32(acc[1][0], pa1.x, pa1.y, pa1.z, pa1.w, b0.x, b0.y);
            mma_tf32(acc[1][1], pa1.x, pa1.y, pa1.z, pa1.w, b0.z, b0.w);
            mma_tf32(acc[1][2], pa1.x, pa1.y, pa1.z, pa1.w, b1.x, b1.y);
            mma_tf32(acc[1][3], pa1.x, pa1.y, pa1.z, pa1.w, b1.z, b1.w);
            mma_tf32(acc[1][4], pa1.x, pa1.y, pa1.z, pa1.w, b2.x, b2.y);
            mma_tf32(acc[1][5], pa1.x, pa1.y, pa1.z, pa1.w, b2.z, b2.w);
            mma_tf32(acc[1][6], pa1.x, pa1.y, pa1.z, pa1.w, b3.x, b3.y);
            mma_tf32(acc[1][7], pa1.x, pa1.y, pa1.z, pa1.w, b3.z, b3.w);
        }
    }

    // epilogue: write ctx in A-permuted tf32 layout (for oproj cp.async)
    #pragma unroll
    for (int mtl = 0; mtl < 2; mtl++) {
        float i0 = 1.0f / l[mtl][0], i1 = 1.0f / l[mtl][1];
        int mt = warp * 2 + mtl;
        #pragma unroll
        for (int nt = 0; nt < 8; nt++) {
            uint32_t base = (((uint32_t)mb * NKT + (h * 8 + nt)) * 8 + mt) * 128 + g * 16;
            g_ctxp[base + t2a * 4 + s2a]     = f2tf(acc[mtl][nt][0] * i0);
            g_ctxp[base + t2b * 4 + s2b]     = f2tf(acc[mtl][nt][1] * i0);
            g_ctxp[base + t2a * 4 + s2a + 1] = f2tf(acc[mtl][nt][2] * i1);
            g_ctxp[base + t2b * 4 + s2b + 1] = f2tf(acc[mtl][nt][3] * i1);
        }
    }
}

// ---------------------------------------------------------------------------
extern "C" void kernel_launch(void* const* d_in, const int* in_sizes, int n_in,
                              void* d_out, int out_size) {
    const float* x  = (const float*)d_in[0];
    const float* Wq = (const float*)d_in[1];
    const float* bq = (const float*)d_in[2];
    const float* Wk = (const float*)d_in[3];
    const float* bk = (const float*)d_in[4];
    const float* Wv = (const float*)d_in[5];
    const float* bv = (const float*)d_in[6];
    const float* Wo = (const float*)d_in[7];
    const float* bo = (const float*)d_in[8];
    const int*   mask = (const int*)d_in[9];
    float* out = (float*)d_out;

    cudaFuncSetAttribute(flash_kernel, cudaFuncAttributeMaxDynamicSharedMemorySize,
                         FLASH_SMEM);
    cudaFuncSetAttribute(proj_kernel, cudaFuncAttributeMaxDynamicSharedMemorySize,
                         GEMM_SMEM);
    cudaFuncSetAttribute(oproj_kernel, cudaFuncAttributeMaxDynamicSharedMemorySize,
                         GEMM_SMEM);

    compact_kernel<<<1, 1024>>>(mask);
    permute_x_kernel<<<dim3(NKT, 32), 256>>>(x);
    permute_w_kernel<<<dim3(NKT, 6, 4), 256>>>(Wq, Wk, Wv, Wo);
    permute_xkv_kernel<<<dim3(NKT, 32), 256>>>(x);
    proj_kernel<<<dim3(6, 32, 3), 256, GEMM_SMEM>>>(bq, bk, bv);
    flash_kernel<<<dim3(SEQ / 128, NHEAD), 128, FLASH_SMEM>>>();
    oproj_kernel<<<dim3(6, 32), 256, GEMM_SMEM>>>(bo, out);
}

// round 10
// speedup vs baseline: 12.4008x; 1.6738x over previous
#include <cuda_runtime.h>
#include <cuda_fp16.h>
#include <math.h>
#include <stdint.h>

#define SEQ  4096
#define HDIM 768
#define NHEAD 12
#define HD   64

#define NKT16 (HDIM / 16)                 // 48 k16-tiles
// A-operand block (128 m x 16 k): 8 subtiles x 32 lanes x 4 words = 1024 words
// B-operand block (128 n x 16 k): 16 subtiles x 32 lanes x 2 words = 1024 words
#define XP_WORDS (32 * NKT16 * 1024)      // 1.57M words
#define WP_WORDS (6  * NKT16 * 1024)

// Scratch (fp16x2 packed in uint32)
__device__ uint32_t g_qp[32 * NHEAD * 4096];     // Q flash-A frags per (mb,h)
__device__ uint32_t g_k2[NHEAD * 64 * 2048];     // K flash-B frags per (h,T)
__device__ uint32_t g_v2[NHEAD * 64 * 2048];     // V flash-B frags per (h,T)
__device__ uint32_t g_xp[XP_WORDS];              // x, GEMM-A layout
__device__ uint32_t g_xkvp[XP_WORDS];            // gathered x, GEMM-A layout
__device__ uint32_t g_ctxp[XP_WORDS];            // ctx, GEMM-A layout
__device__ uint32_t g_wp[4][WP_WORDS];           // W*, GEMM-B layout
__device__ int      g_kidx[SEQ];
__device__ int      g_cnt;

__device__ __forceinline__ uint32_t pack2(float lo, float hi) {
    __half2 h = __floats2half2_rn(lo, hi);   // x = lo (low 16 bits), y = hi
    return *(uint32_t*)&h;
}

__device__ __forceinline__ void mma_f16(float c[4],
                                        uint32_t a0, uint32_t a1, uint32_t a2, uint32_t a3,
                                        uint32_t b0, uint32_t b1) {
    asm volatile("mma.sync.aligned.m16n8k16.row.col.f32.f16.f16.f32 "
                 "{%0,%1,%2,%3}, {%4,%5,%6,%7}, {%8,%9}, {%0,%1,%2,%3};"
                 : "+f"(c[0]), "+f"(c[1]), "+f"(c[2]), "+f"(c[3])
                 : "r"(a0), "r"(a1), "r"(a2), "r"(a3), "r"(b0), "r"(b1));
}

__device__ __forceinline__ void cp16(uint32_t smem_addr, const void* gptr) {
    asm volatile("cp.async.cg.shared.global [%0], [%1], 16;"
                 :: "r"(smem_addr), "l"(gptr));
}
#define CP_COMMIT() asm volatile("cp.async.commit_group;")
#define CP_WAIT1()  asm volatile("cp.async.wait_group 1;")
#define CP_WAIT2()  asm volatile("cp.async.wait_group 2;")

// ---------------------------------------------------------------------------
// Compaction (unchanged)
// ---------------------------------------------------------------------------
__global__ void compact_kernel(const int* __restrict__ mask) {
    __shared__ int wsum[32];
    int tid = threadIdx.x, lane = tid & 31, wid = tid >> 5;
    int f[4];
    int c = 0;
    #pragma unroll
    for (int r = 0; r < 4; r++) {
        f[r] = (mask[tid * 4 + r] == 0) ? 1 : 0;
        c += f[r];
    }
    int inc = c;
    #pragma unroll
    for (int o = 1; o < 32; o <<= 1) {
        int n = __shfl_up_sync(0xffffffffu, inc, o);
        if (lane >= o) inc += n;
    }
    if (lane == 31) wsum[wid] = inc;
    __syncthreads();
    if (wid == 0) {
        int v = wsum[lane];
        int s = v;
        #pragma unroll
        for (int o = 1; o < 32; o <<= 1) {
            int n = __shfl_up_sync(0xffffffffu, s, o);
            if (lane >= o) s += n;
        }
        wsum[lane] = s - v;
        if (lane == 31) g_cnt = s;
    }
    __syncthreads();
    int base = wsum[wid] + inc - c;
    #pragma unroll
    for (int r = 0; r < 4; r++) {
        if (f[r]) g_kidx[base++] = tid * 4 + r;
    }
}

// ---------------------------------------------------------------------------
// Permute x -> g_xp (GEMM-A fp16 fragments). grid (48, 32), block 256.
// A subtile word wi @ lane l: m = st*16+(wi&1)*8+(l>>2), k-pair = (wi>>1)*8+2(l&3)
// ---------------------------------------------------------------------------
__global__ __launch_bounds__(256)
void permute_x_kernel(const float* __restrict__ x) {
    int kt = blockIdx.x, mb = blockIdx.y;
    int st = threadIdx.x >> 5, l = threadIdx.x & 31;
    uint32_t w[4];
    #pragma unroll
    for (int wi = 0; wi < 4; wi++) {
        int m = mb * 128 + st * 16 + (wi & 1) * 8 + (l >> 2);
        int k = kt * 16 + (wi >> 1) * 8 + 2 * (l & 3);
        const float* p = x + (size_t)m * HDIM + k;
        w[wi] = pack2(p[0], p[1]);
    }
    *(uint4*)&g_xp[((size_t)(mb * NKT16 + kt) * 8 + st) * 128 + l * 4] = *(uint4*)w;
}

__global__ __launch_bounds__(256)
void permute_xkv_kernel(const float* __restrict__ x) {
    int kt = blockIdx.x, mb = blockIdx.y;
    int cnt = g_cnt;
    if (mb * 128 >= cnt) return;
    int st = threadIdx.x >> 5, l = threadIdx.x & 31;
    uint32_t w[4];
    #pragma unroll
    for (int wi = 0; wi < 4; wi++) {
        int m = mb * 128 + st * 16 + (wi & 1) * 8 + (l >> 2);
        int k = kt * 16 + (wi >> 1) * 8 + 2 * (l & 3);
        float v0 = 0.f, v1 = 0.f;
        if (m < cnt) {
            const float* p = x + (size_t)g_kidx[m] * HDIM + k;
            v0 = p[0]; v1 = p[1];
        }
        w[wi] = pack2(v0, v1);
    }
    *(uint4*)&g_xkvp[((size_t)(mb * NKT16 + kt) * 8 + st) * 128 + l * 4] = *(uint4*)w;
}

// ---------------------------------------------------------------------------
// Permute W -> g_wp[z] (GEMM-B fp16 fragments). grid (48, 6, 4), block 256.
// B subtile word wi @ lane l: n = nt*8+(l>>2), k-pair = wi*8+2(l&3)
// ---------------------------------------------------------------------------
__global__ __launch_bounds__(256)
void permute_w_kernel(const float* __restrict__ Wq, const float* __restrict__ Wk,
                      const float* __restrict__ Wv, const float* __restrict__ Wo) {
    int kt = blockIdx.x, nb = blockIdx.y, z = blockIdx.z;
    const float* W = (z == 0) ? Wq : (z == 1) ? Wk : (z == 2) ? Wv : Wo;
    int st2 = threadIdx.x >> 5, l = threadIdx.x & 31;
    #pragma unroll
    for (int u = 0; u < 2; u++) {
        int nt = st2 * 2 + u;
        uint32_t w[2];
        #pragma unroll
        for (int wi = 0; wi < 2; wi++) {
            int n = nb * 128 + nt * 8 + (l >> 2);
            int k = kt * 16 + wi * 8 + 2 * (l & 3);
            const float* p = W + (size_t)n * HDIM + k;
            w[wi] = pack2(p[0], p[1]);
        }
        *(uint2*)&g_wp[z][((size_t)(nb * NKT16 + kt)) * 1024 + (nt * 32 + l) * 2] =
            *(uint2*)w;
    }
}

// ---------------------------------------------------------------------------
// fp16 GEMM mainloop: CTA 128x128, BK=32 (2 k16-tiles/stage), 3-stage cp.async
// pipeline, 256 thr = 8 warps (4m x 2n), warp tile 32x64.
// Stage = A 8KB + B 8KB. Dyn smem 48KB.
// ---------------------------------------------------------------------------
__device__ __forceinline__ void gemm_main(uint32_t* sg,
                                          const uint32_t* __restrict__ Ap,
                                          const uint32_t* __restrict__ Bp,
                                          float acc[2][8][4]) {
    int tid = threadIdx.x;
    int lane = tid & 31, warp = tid >> 5;
    int warp_m = warp & 3, warp_n = warp >> 2;
    uint32_t smem_base = (uint32_t)__cvta_generic_to_shared(sg);

    const uint4* Asrc = (const uint4*)Ap;
    const uint4* Bsrc = (const uint4*)Bp;

    auto pf = [&](int s, int st) {
        uint32_t da = smem_base + (uint32_t)st * 16384u;
        const uint4* a = Asrc + (size_t)s * 512;
        const uint4* b = Bsrc + (size_t)s * 512;
        #pragma unroll
        for (int i = 0; i < 2; i++) {
            int o = i * 256 + tid;
            cp16(da + (uint32_t)o * 16u, a + o);
            cp16(da + 8192u + (uint32_t)o * 16u, b + o);
        }
    };

    pf(0, 0); CP_COMMIT();
    pf(1, 1); CP_COMMIT();
    pf(2, 2); CP_COMMIT();

    const int NST = HDIM / 32;   // 24 stages
    for (int s = 0; s < NST; s++) {
        CP_WAIT2();
        __syncthreads();
        uint32_t* A = sg + (s % 3) * 4096;
        uint32_t* B = A + 2048;
        #pragma unroll
        for (int kt = 0; kt < 2; kt++) {
            const uint32_t* Ak = A + kt * 1024;
            const uint32_t* Bk = B + kt * 1024;
            uint4 a0 = *(const uint4*)&Ak[((warp_m * 2 + 0) * 32 + lane) * 4];
            uint4 a1 = *(const uint4*)&Ak[((warp_m * 2 + 1) * 32 + lane) * 4];
            #pragma unroll
            for (int nt = 0; nt < 8; nt++) {
                uint2 b = *(const uint2*)&Bk[((warp_n * 8 + nt) * 32 + lane) * 2];
                mma_f16(acc[0][nt], a0.x, a0.y, a0.z, a0.w, b.x, b.y);
                mma_f16(acc[1][nt], a1.x, a1.y, a1.z, a1.w, b.x, b.y);
            }
        }
        __syncthreads();
        if (s + 3 < NST) pf(s + 3, s % 3);
        CP_COMMIT();
    }
}

#define GEMM_SMEM (3 * 4096 * 4)

// ---------------------------------------------------------------------------
// Projection kernel. z=0: Q (M=4096) -> g_qp (flash-A frags, fp16).
// z=1: K (M=cnt) -> g_k2 (flash-B frags). z=2: V -> g_v2.
// grid (6, 32, 3), block 256.
// ---------------------------------------------------------------------------
__global__ __launch_bounds__(256)
void proj_kernel(const float* __restrict__ bq, const float* __restrict__ bk,
                 const float* __restrict__ bv) {
    extern __shared__ uint32_t sg[];
    int z = blockIdx.z;
    int mb = blockIdx.y;
    int cnt = g_cnt;
    if (z > 0 && mb * 128 >= cnt) return;

    const uint32_t* Ap = ((z == 0) ? g_xp : g_xkvp) + (size_t)mb * NKT16 * 1024;
    const uint32_t* Bp = g_wp[z] + (size_t)blockIdx.x * NKT16 * 1024;
    const float* bias = (z == 0) ? bq : (z == 1) ? bk : bv;

    float acc[2][8][4] = {};
    gemm_main(sg, Ap, Bp, acc);

    int tid = threadIdx.x;
    int lane = tid & 31, warp = tid >> 5;
    int g = lane >> 2, tg = lane & 3;
    int warp_m = warp & 3, warp_n = warp >> 2;
    int h = blockIdx.x * 2 + warp_n;

    if (z == 0) {
        // Q -> flash-A frags; word ((kt*8+mt)*32+lane)*4 + wi, wi = rowhalf + (nt&1)*2
        uint32_t* dst = g_qp + (size_t)(mb * NHEAD + h) * 4096;
        #pragma unroll
        for (int i = 0; i < 2; i++) {
            int mt = warp_m * 2 + i;
            #pragma unroll
            for (int nt = 0; nt < 8; nt++) {
                int dd0 = nt * 8 + 2 * tg;
                float bx = bias[h * 64 + dd0], by = bias[h * 64 + dd0 + 1];
                int kt = nt >> 1;
                uint32_t o = (uint32_t)((kt * 8 + mt) * 32 + lane) * 4 + (nt & 1) * 2;
                uint2 v;
                v.x = pack2(acc[i][nt][0] + bx, acc[i][nt][1] + by);   // row g
                v.y = pack2(acc[i][nt][2] + bx, acc[i][nt][3] + by);   // row g+8
                *(uint2*)&dst[o] = v;
            }
        }
    } else if (z == 1) {
        // K -> flash-B frags per (h,T): word ((ntK*2+ktp)*32 + (jj&7)*4+tg)*4 + wi
        #pragma unroll
        for (int i = 0; i < 2; i++) {
            int j0 = mb * 128 + warp_m * 32 + i * 16 + g;
            #pragma unroll
            for (int nt = 0; nt < 8; nt++) {
                int dd0 = nt * 8 + 2 * tg;
                float bx = bias[h * 64 + dd0], by = bias[h * 64 + dd0 + 1];
                int ktp = nt >> 2;
                int wi = ((nt >> 1) & 1) * 2 + (nt & 1);
                #pragma unroll
                for (int r = 0; r < 2; r++) {
                    int j = j0 + r * 8;
                    int T = j >> 6, jj = j & 63;
                    uint32_t base = (uint32_t)(h * 64 + T) * 2048;
                    uint32_t o = base + (uint32_t)(((jj >> 3) * 2 + ktp) * 32
                                 + (jj & 7) * 4 + tg) * 4 + wi;
                    g_k2[o] = pack2(acc[i][nt][r * 2 + 0] + bx,
                                    acc[i][nt][r * 2 + 1] + by);
                }
            }
        }
    } else {
        // V -> flash-B frags (pairs along j): scalar half stores
        __half* dst = (__half*)g_v2;
        #pragma unroll
        for (int i = 0; i < 2; i++) {
            int j0 = mb * 128 + warp_m * 32 + i * 16 + g;
            #pragma unroll
            for (int nt = 0; nt < 8; nt++) {
                int dd0 = nt * 8 + 2 * tg;
                float bx = bias[h * 64 + dd0], by = bias[h * 64 + dd0 + 1];
                #pragma unroll
                for (int r = 0; r < 2; r++) {
                    int j = j0 + r * 8;
                    int T = j >> 6, jj = j & 63;
                    int wi = ((jj >> 4) & 1) * 2 + ((jj >> 3) & 1);
                    int ktp = jj >> 5;
                    int lq = (jj >> 1) & 3;
                    int e = jj & 1;
                    #pragma unroll
                    for (int c = 0; c < 2; c++) {
                        int dd = dd0 + c;
                        int l = (dd & 7) * 4 + lq;
                        size_t hidx = (((size_t)(h * 64 + T) * 2048
                                      + ((dd >> 3) * 2 + ktp) * 128 + (l * 4 + wi))) * 2 + e;
                        dst[hidx] = __float2half_rn(acc[i][nt][r * 2 + c] + (c ? by : bx));
                    }
                }
            }
        }
    }
}

__global__ __launch_bounds__(256)
void oproj_kernel(const float* __restrict__ bo, float* __restrict__ out) {
    extern __shared__ uint32_t sg[];
    int mb = blockIdx.y;
    float acc[2][8][4] = {};
    gemm_main(sg, g_ctxp + (size_t)mb * NKT16 * 1024,
              g_wp[3] + (size_t)blockIdx.x * NKT16 * 1024, acc);

    int tid = threadIdx.x;
    int lane = tid & 31, warp = tid >> 5;
    int g = lane >> 2, tg = lane & 3;
    int warp_m = warp & 3, warp_n = warp >> 2;
    int mbase = mb * 128, nbase = blockIdx.x * 128;
    #pragma unroll
    for (int i = 0; i < 2; i++) {
        int m0 = mbase + warp_m * 32 + i * 16 + g;
        #pragma unroll
        for (int nt = 0; nt < 8; nt++) {
            int n0 = nbase + warp_n * 64 + nt * 8 + 2 * tg;
            float bx = bo[n0], by = bo[n0 + 1];
            *(float2*)(out + (size_t)m0 * HDIM + n0) =
                make_float2(acc[i][nt][0] + bx, acc[i][nt][1] + by);
            *(float2*)(out + (size_t)(m0 + 8) * HDIM + n0) =
                make_float2(acc[i][nt][2] + bx, acc[i][nt][3] + by);
        }
    }
}

// ---------------------------------------------------------------------------
// Flash attention, fp16 m16n8k16. CTA = (head, 128 q), 128 thr = 4 warps x m32.
// Q frags from g_qp (8 LDG.128). K/V double-buffered cp.async (16KB/tile).
// P re-fragmentation is free (C-frag pairs pack directly into A-frag words).
// Smem: 2 x (K 8KB + V 8KB) = 32KB. Epilogue -> g_ctxp (GEMM-A frags).
// ---------------------------------------------------------------------------
#define FLASH_SMEM (8192 * 4)

__global__ __launch_bounds__(128)
void flash_kernel() {
    extern __shared__ uint32_t sm[];
    int tid = threadIdx.x;
    int lane = tid & 31, warp = tid >> 5;
    int g = lane >> 2, tg = lane & 3;
    int h = blockIdx.y, mb = blockIdx.x;
    int cnt = g_cnt;
    uint32_t smem_base = (uint32_t)__cvta_generic_to_shared(sm);

    const uint4* Ksrc = (const uint4*)(g_k2 + (size_t)h * 64 * 2048);
    const uint4* Vsrc = (const uint4*)(g_v2 + (size_t)h * 64 * 2048);
    int ntile = (cnt + 63) >> 6;

    auto prefetch = [&](int t, int buf) {
        uint32_t dk = smem_base + (uint32_t)buf * 16384u;
        const uint4* sk = Ksrc + (size_t)t * 512;
        const uint4* sv = Vsrc + (size_t)t * 512;
        #pragma unroll
        for (int i = 0; i < 4; i++) {
            int o = i * 128 + tid;
            cp16(dk + (uint32_t)o * 16u, sk + o);
            cp16(dk + 8192u + (uint32_t)o * 16u, sv + o);
        }
    };

    prefetch(0, 0);
    CP_COMMIT();

    // Q fragments (overlap with first prefetch)
    const uint32_t* Qsrc = g_qp + (size_t)(mb * NHEAD + h) * 4096;
    uint4 q[4][2];
    #pragma unroll
    for (int kt = 0; kt < 4; kt++)
        #pragma unroll
        for (int mtl = 0; mtl < 2; mtl++)
            q[kt][mtl] = *(const uint4*)&Qsrc[((kt * 8 + warp * 2 + mtl) * 32 + lane) * 4];

    float m[2][2] = {{-1e30f, -1e30f}, {-1e30f, -1e30f}};
    float l[2][2] = {{0.f, 0.f}, {0.f, 0.f}};
    float acc[2][8][4] = {};

    for (int t = 0; t < ntile; t++) {
        int cur = t & 1;
        int kvb = t * 64;
        __syncthreads();
        if (t + 1 < ntile) prefetch(t + 1, cur ^ 1);
        CP_COMMIT();
        CP_WAIT1();
        __syncthreads();
        uint32_t* Kp = sm + cur * 4096;
        uint32_t* Vp = Kp + 2048;

        // S = Q K^T (warp: 32x64): 2 ktp x 8 nt x (2 kt x 2 mtl) mma
        float sc[2][8][4] = {};
        #pragma unroll
        for (int ktp = 0; ktp < 2; ktp++) {
            #pragma unroll
            for (int nt = 0; nt < 8; nt++) {
                uint4 kb = *(const uint4*)&Kp[((nt * 2 + ktp) * 32 + lane) * 4];
                #pragma unroll
                for (int mtl = 0; mtl < 2; mtl++) {
                    uint4 a = q[2 * ktp][mtl];
                    mma_f16(sc[mtl][nt], a.x, a.y, a.z, a.w, kb.x, kb.y);
                    uint4 a2 = q[2 * ktp + 1][mtl];
                    mma_f16(sc[mtl][nt], a2.x, a2.y, a2.z, a2.w, kb.z, kb.w);
                }
            }
        }

        bool tail = (kvb + 64 > cnt);

        uint32_t pA[4][2][4];
        #pragma unroll
        for (int mtl = 0; mtl < 2; mtl++) {
            #pragma unroll
            for (int nt = 0; nt < 8; nt++) {
                #pragma unroll
                for (int e = 0; e < 4; e++)
                    sc[mtl][nt][e] *= 0.125f;
            }
            if (tail) {
                #pragma unroll
                for (int nt = 0; nt < 8; nt++) {
                    int c0 = kvb + nt * 8 + 2 * tg;
                    if (c0     >= cnt) { sc[mtl][nt][0] = -1e30f; sc[mtl][nt][2] = -1e30f; }
                    if (c0 + 1 >= cnt) { sc[mtl][nt][1] = -1e30f; sc[mtl][nt][3] = -1e30f; }
                }
            }

            float rm0 = -1e30f, rm1 = -1e30f;
            #pragma unroll
            for (int nt = 0; nt < 8; nt++) {
                rm0 = fmaxf(rm0, fmaxf(sc[mtl][nt][0], sc[mtl][nt][1]));
                rm1 = fmaxf(rm1, fmaxf(sc[mtl][nt][2], sc[mtl][nt][3]));
            }
            rm0 = fmaxf(rm0, __shfl_xor_sync(0xffffffffu, rm0, 1));
            rm0 = fmaxf(rm0, __shfl_xor_sync(0xffffffffu, rm0, 2));
            rm1 = fmaxf(rm1, __shfl_xor_sync(0xffffffffu, rm1, 1));
            rm1 = fmaxf(rm1, __shfl_xor_sync(0xffffffffu, rm1, 2));

            float mn0 = fmaxf(m[mtl][0], rm0), mn1 = fmaxf(m[mtl][1], rm1);
            float al0 = __expf(m[mtl][0] - mn0), al1 = __expf(m[mtl][1] - mn1);
            float rs0 = 0.f, rs1 = 0.f;
            #pragma unroll
            for (int nt = 0; nt < 8; nt++) {
                float p0 = __expf(sc[mtl][nt][0] - mn0); sc[mtl][nt][0] = p0; rs0 += p0;
                float p1 = __expf(sc[mtl][nt][1] - mn0); sc[mtl][nt][1] = p1; rs0 += p1;
                float p2 = __expf(sc[mtl][nt][2] - mn1); sc[mtl][nt][2] = p2; rs1 += p2;
                float p3 = __expf(sc[mtl][nt][3] - mn1); sc[mtl][nt][3] = p3; rs1 += p3;
            }
            rs0 += __shfl_xor_sync(0xffffffffu, rs0, 1);
            rs0 += __shfl_xor_sync(0xffffffffu, rs0, 2);
            rs1 += __shfl_xor_sync(0xffffffffu, rs1, 1);
            rs1 += __shfl_xor_sync(0xffffffffu, rs1, 2);
            l[mtl][0] = l[mtl][0] * al0 + rs0; m[mtl][0] = mn0;
            l[mtl][1] = l[mtl][1] * al1 + rs1; m[mtl][1] = mn1;
            #pragma unroll
            for (int nt = 0; nt < 8; nt++) {
                acc[mtl][nt][0] *= al0; acc[mtl][nt][1] *= al0;
                acc[mtl][nt][2] *= al1; acc[mtl][nt][3] *= al1;
            }

            // Pack P into fp16 A fragments (free re-fragmentation)
            #pragma unroll
            for (int kt = 0; kt < 4; kt++) {
                pA[kt][mtl][0] = pack2(sc[mtl][2 * kt][0],     sc[mtl][2 * kt][1]);
                pA[kt][mtl][1] = pack2(sc[mtl][2 * kt][2],     sc[mtl][2 * kt][3]);
                pA[kt][mtl][2] = pack2(sc[mtl][2 * kt + 1][0], sc[mtl][2 * kt + 1][1]);
                pA[kt][mtl][3] = pack2(sc[mtl][2 * kt + 1][2], sc[mtl][2 * kt + 1][3]);
            }
        }

        // acc += P @ V
        #pragma unroll
        for (int ktp = 0; ktp < 2; ktp++) {
            #pragma unroll
            for (int nt = 0; nt < 8; nt++) {
                uint4 vb = *(const uint4*)&Vp[((nt * 2 + ktp) * 32 + lane) * 4];
                #pragma unroll
                for (int mtl = 0; mtl < 2; mtl++) {
                    uint32_t* a = pA[2 * ktp][mtl];
                    mma_f16(acc[mtl][nt], a[0], a[1], a[2], a[3], vb.x, vb.y);
                    uint32_t* a2 = pA[2 * ktp + 1][mtl];
                    mma_f16(acc[mtl][nt], a2[0], a2[1], a2[2], a2[3], vb.z, vb.w);
                }
            }
        }
    }

    // epilogue: ctx -> g_ctxp (GEMM-A fp16 fragments)
    #pragma unroll
    for (int mtl = 0; mtl < 2; mtl++) {
        float i0 = 1.0f / l[mtl][0], i1 = 1.0f / l[mtl][1];
        int mt = warp * 2 + mtl;
        #pragma unroll
        for (int nt = 0; nt < 8; nt++) {
            int kt16 = h * 4 + (nt >> 1);
            uint32_t o = ((uint32_t)(mb * NKT16 + kt16) * 8 + mt) * 128
                       + lane * 4 + (nt & 1) * 2;
            uint2 v;
            v.x = pack2(acc[mtl][nt][0] * i0, acc[mtl][nt][1] * i0);   // row g
            v.y = pack2(acc[mtl][nt][2] * i1, acc[mtl][nt][3] * i1);   // row g+8
            *(uint2*)&g_ctxp[o] = v;
        }
    }
}

// ---------------------------------------------------------------------------
extern "C" void kernel_launch(void* const* d_in, const int* in_sizes, int n_in,
                              void* d_out, int out_size) {
    const float* x  = (const float*)d_in[0];
    const float* Wq = (const float*)d_in[1];
    const float* bq = (const float*)d_in[2];
    const float* Wk = (const float*)d_in[3];
    const float* bk = (const float*)d_in[4];
    const float* Wv = (const float*)d_in[5];
    const float* bv = (const float*)d_in[6];
    const float* Wo = (const float*)d_in[7];
    const float* bo = (const float*)d_in[8];
    const int*   mask = (const int*)d_in[9];
    float* out = (float*)d_out;

    cudaFuncSetAttribute(flash_kernel, cudaFuncAttributeMaxDynamicSharedMemorySize,
                         FLASH_SMEM);
    cudaFuncSetAttribute(proj_kernel, cudaFuncAttributeMaxDynamicSharedMemorySize,
                         GEMM_SMEM);
    cudaFuncSetAttribute(oproj_kernel, cudaFuncAttributeMaxDynamicSharedMemorySize,
                         GEMM_SMEM);

    compact_kernel<<<1, 1024>>>(mask);
    permute_x_kernel<<<dim3(NKT16, 32), 256>>>(x);
    permute_w_kernel<<<dim3(NKT16, 6, 4), 256>>>(Wq, Wk, Wv, Wo);
    permute_xkv_kernel<<<dim3(NKT16, 32), 256>>>(x);
    proj_kernel<<<dim3(6, 32, 3), 256, GEMM_SMEM>>>(bq, bk, bv);
    flash_kernel<<<dim3(SEQ / 128, NHEAD), 128, FLASH_SMEM>>>();
    oproj_kernel<<<dim3(6, 32), 256, GEMM_SMEM>>>(bo, out);
}